// round 13
// baseline (speedup 1.0000x reference)
#include <cuda_runtime.h>
#include <cuda_fp16.h>
#include <math.h>
#include <stdint.h>

#define Bz   4
#define Tt   512
#define Dd   768
#define Hh   8
#define HDim 96
#define HDP  128            // padded head dim for MMA (pad cols stay zero: globals zero-init)
#define Ll   12
#define Vv   50257
#define MR   (Bz*Tt)
#define BH   (Bz*Hh)
#define ATT_SCALE 0.10206207261596575f

__device__ __forceinline__ uint32_t smem_u32(const void* p) {
    uint32_t a;
    asm("{ .reg .u64 t; cvta.to.shared.u64 t, %1; cvt.u32.u64 %0, t; }" : "=r"(a) : "l"(p));
    return a;
}

// ---------------- scratch (device globals) ----------------
__device__ float g_x [MR*Dd];
__device__ __align__(16) __half g_h16[MR*Dd];
__device__ __align__(16) __half g_f16[MR*4*Dd];
__device__ __align__(16) __half g_qh[(size_t)BH*Tt*HDP], g_ql[(size_t)BH*Tt*HDP];
__device__ __align__(16) __half g_kh[(size_t)BH*Tt*HDP], g_kl[(size_t)BH*Tt*HDP];
__device__ __align__(16) __half g_vth[(size_t)BH*HDim*Tt];
__device__ __align__(16) __half g_oh[MR*Dd];
__device__ __align__(16) __half g_wq[(size_t)Ll*3*Dd*Dd];
__device__ __align__(16) __half g_wo[(size_t)Ll*Dd*Dd];
__device__ __align__(16) __half g_w1[(size_t)Ll*4*Dd*Dd];
__device__ __align__(16) __half g_w2[(size_t)Ll*4*Dd*Dd];
__device__ __align__(16) __half g_wh[(size_t)Vv*Dd];

// ---------------- weight fp32 -> fp16 ----------------
__global__ void cvt_k(const float* __restrict__ w, __half* __restrict__ o, size_t n4) {
    size_t i = (size_t)blockIdx.x * 256 + threadIdx.x;
    if (i >= n4) return;
    float4 v = ((const float4*)w)[i];
    ((__half2*)o)[i * 2]     = __floats2half2_rn(v.x, v.y);
    ((__half2*)o)[i * 2 + 1] = __floats2half2_rn(v.z, v.w);
}

// ---------------- embedding ----------------
__global__ void embed_k(const int* __restrict__ idx, const float* __restrict__ tok,
                        const float* __restrict__ pos, float* __restrict__ x) {
    int i = blockIdx.x * 256 + threadIdx.x;
    int m = i / Dd, d = i - m * Dd;
    int t = m & (Tt - 1);
    x[i] = tok[(size_t)idx[m] * Dd + d] + pos[t * Dd + d];
}

// ---------------- layernorm -> fp16 (+ optional fp32) ----------------
__global__ void ln_k(const float* __restrict__ in, const float* __restrict__ s,
                     const float* __restrict__ b, __half* __restrict__ oh,
                     float* __restrict__ ofp) {
    int m = blockIdx.x, tid = threadIdx.x;
    const float* row = in + (size_t)m * Dd;
    float x0 = row[tid], x1 = row[tid + 256], x2 = row[tid + 512];
    __shared__ float red[256];
    red[tid] = x0 + x1 + x2;
    __syncthreads();
    #pragma unroll
    for (int st = 128; st > 0; st >>= 1) { if (tid < st) red[tid] += red[tid + st]; __syncthreads(); }
    float mean = red[0] * (1.0f / Dd);
    __syncthreads();
    float d0 = x0 - mean, d1 = x1 - mean, d2 = x2 - mean;
    red[tid] = d0 * d0 + d1 * d1 + d2 * d2;
    __syncthreads();
    #pragma unroll
    for (int st = 128; st > 0; st >>= 1) { if (tid < st) red[tid] += red[tid + st]; __syncthreads(); }
    float inv = rsqrtf(red[0] * (1.0f / Dd) + 1e-5f);
    size_t base = (size_t)m * Dd;
    #pragma unroll
    for (int q = 0; q < 3; q++) {
        int c = tid + q * 256;
        float dv = (q == 0 ? d0 : (q == 1 ? d1 : d2));
        float v = dv * inv * s[c] + b[c];
        oh[base + c] = __float2half(v);
        if (ofp) ofp[base + c] = v;
    }
}

// ---------------- HMMA primitives ----------------
__device__ __forceinline__ void ldsm4(uint32_t& r0, uint32_t& r1, uint32_t& r2, uint32_t& r3,
                                      uint32_t addr) {
    asm volatile("ldmatrix.sync.aligned.m8n8.x4.shared.b16 {%0,%1,%2,%3}, [%4];"
                 : "=r"(r0), "=r"(r1), "=r"(r2), "=r"(r3) : "r"(addr));
}
__device__ __forceinline__ void mma16816(float* d, const uint32_t* a, const uint32_t* b) {
    asm volatile("mma.sync.aligned.m16n8k16.row.col.f32.f16.f16.f32 "
                 "{%0,%1,%2,%3}, {%4,%5,%6,%7}, {%8,%9}, {%0,%1,%2,%3};"
                 : "+f"(d[0]), "+f"(d[1]), "+f"(d[2]), "+f"(d[3])
                 : "r"(a[0]), "r"(a[1]), "r"(a[2]), "r"(a[3]), "r"(b[0]), "r"(b[1]));
}

#define ROWB 144

// ---------------- templated fp16 GEMM: C[M,N] = A[M,K]*B[N,K]^T, fp32 acc ------
// CTA tile 128 x (NT*32); 8 warps as 2x4; warp tile 64 x (NT*8). K-chunk 64,
// cp.async double buffer. mode: 0 normal | 1 gelu(bias) | 2 qkv split scatter.
// swapxy: m from blockIdx.x (fast) -> concurrent CTAs share B tiles.
template<int NT, int MINB>
__global__ __launch_bounds__(256, MINB) void gemm_mm(
    const __half* __restrict__ A, const __half* __restrict__ Bm,
    int N, int K,
    const float* __restrict__ bias, const float* __restrict__ resid,
    float* __restrict__ Cf, __half* __restrict__ Ch, int mode, int swapxy)
{
    constexpr int CTA_N = NT * 32;
    constexpr int OPB_A = 128 * ROWB;
    constexpr int OPB_B = CTA_N * ROWB;
    constexpr int STGT  = OPB_A + OPB_B;
    constexpr int NXFER = (128 + CTA_N) * 8;      // 16B transfers per chunk

    extern __shared__ char smem[];
    uint32_t sb = smem_u32(smem);
    int tid = threadIdx.x, wid = tid >> 5, lane = tid & 31;
    int wm = wid >> 2, wn = wid & 3;
    int m0 = (swapxy ? blockIdx.x : blockIdx.y) * 128;
    int n0 = (swapxy ? blockIdx.y : blockIdx.x) * CTA_N;

    auto load_chunk = [&](int c) {
        int kt = c << 6;
        uint32_t st = sb + (c & 1) * STGT;
        #pragma unroll
        for (int o = 0; o < NXFER / 256; o++) {
            int flat = o * 256 + tid;
            uint32_t dst;
            const __half* src;
            if (flat < 1024) {                    // A: 128 rows x 8
                int row = flat >> 3, c16 = flat & 7;
                dst = st + row * ROWB + c16 * 16;
                src = A + (size_t)(m0 + row) * K + kt + c16 * 8;
            } else {                              // B: CTA_N rows x 8
                int v = flat - 1024;
                int row = v >> 3, c16 = v & 7;
                dst = st + OPB_A + row * ROWB + c16 * 16;
                int r = n0 + row; if (r >= N) r = N - 1;
                src = Bm + (size_t)r * K + kt + c16 * 8;
            }
            asm volatile("cp.async.cg.shared.global [%0], [%1], 16;" :: "r"(dst), "l"(src));
        }
        asm volatile("cp.async.commit_group;" ::: "memory");
    };

    float acc[4][NT][4] = {};
    int nc = K >> 6;

    load_chunk(0);
    load_chunk(1);

    for (int c = 0; c < nc; c++) {
        if (c + 1 < nc) asm volatile("cp.async.wait_group 1;" ::: "memory");
        else            asm volatile("cp.async.wait_group 0;" ::: "memory");
        __syncthreads();
        uint32_t st = sb + (c & 1) * STGT;
        uint32_t a_row = (uint32_t)(wm * 64 + (lane & 15)) * ROWB + (lane >> 4) * 16;
        uint32_t b_row = (uint32_t)(wn * CTA_N / 4 + (lane & 7) + ((lane >> 4) & 1) * 8) * ROWB
                       + ((lane >> 3) & 1) * 16;
        #pragma unroll
        for (int kk = 0; kk < 4; kk++) {
            uint32_t ah[4][4], bh[NT][2];
            #pragma unroll
            for (int mt = 0; mt < 4; mt++) {
                uint32_t ad = st + a_row + mt * (16 * ROWB) + kk * 32;
                ldsm4(ah[mt][0], ah[mt][1], ah[mt][2], ah[mt][3], ad);
            }
            #pragma unroll
            for (int np = 0; np < NT / 2; np++) {
                uint32_t bd = st + OPB_A + b_row + np * (16 * ROWB) + kk * 32;
                ldsm4(bh[np*2][0], bh[np*2][1], bh[np*2+1][0], bh[np*2+1][1], bd);
            }
            #pragma unroll
            for (int mt = 0; mt < 4; mt++)
                #pragma unroll
                for (int nt = 0; nt < NT; nt++)
                    mma16816(acc[mt][nt], ah[mt], bh[nt]);
        }
        __syncthreads();
        if (c + 2 < nc) load_chunk(c + 2);
    }

    #pragma unroll
    for (int mt = 0; mt < 4; mt++) {
        #pragma unroll
        for (int nt = 0; nt < NT; nt++) {
            int mbase = m0 + wm * 64 + mt * 16 + (lane >> 2);
            int nbase = n0 + wn * (NT * 8) + nt * 8 + (lane & 3) * 2;
            #pragma unroll
            for (int hrow = 0; hrow < 2; hrow++) {
                int m = mbase + hrow * 8;
                #pragma unroll
                for (int jj = 0; jj < 2; jj++) {
                    int n = nbase + jj;
                    float v = acc[mt][nt][hrow * 2 + jj];
                    if (mode == 2) {
                        int sct = n / Dd, r = n - sct * Dd;
                        int h = r / HDim, hd = r - h * HDim;
                        int bb = m >> 9, t = m & (Tt - 1);
                        int bh_ = bb * Hh + h;
                        if (sct == 0) {
                            size_t ix = ((size_t)bh_ * Tt + t) * HDP + hd;
                            __half hv = __float2half(v);
                            g_qh[ix] = hv;
                            g_ql[ix] = __float2half(v - __half2float(hv));
                        } else if (sct == 1) {
                            size_t ix = ((size_t)bh_ * Tt + t) * HDP + hd;
                            __half hv = __float2half(v);
                            g_kh[ix] = hv;
                            g_kl[ix] = __float2half(v - __half2float(hv));
                        } else {
                            g_vth[((size_t)bh_ * HDim + hd) * Tt + t] = __float2half(v);
                        }
                    } else if (n < N) {
                        if (bias) v += bias[n];
                        if (mode == 1) v = 0.5f * v * (1.0f + erff(v * 0.70710678118654752f));
                        size_t ix = (size_t)m * N + n;
                        if (resid) v += resid[ix];
                        if (Cf) Cf[ix] = v;
                        if (Ch) Ch[ix] = __float2half(v);
                    }
                }
            }
        }
    }
}

#define SMEM_MM4 (2*(128+128)*ROWB)   // 73728
#define SMEM_MM8 (2*(128+256)*ROWB)   // 110592

// ---------------- fused flash attention (proven in R10; unchanged) ----------------
#define QROWB 272
#define VROWB 144
#define FQ_OP (128*QROWB)
#define FK_OP (64*QROWB)
#define FV_OP (96*VROWB)
#define FSTGB (2*FK_OP + FV_OP)
#define SMEM_FA (2*FQ_OP + 2*FSTGB)  // 166912

__global__ __launch_bounds__(256, 1) void flash_attn(
    const __half* __restrict__ Qh, const __half* __restrict__ Ql,
    const __half* __restrict__ Kh, const __half* __restrict__ Kl,
    const __half* __restrict__ Vt, __half* __restrict__ Oo)
{
    extern __shared__ char smem[];
    uint32_t sb = smem_u32(smem);
    int tid = threadIdx.x, wid = tid >> 5, lane = tid & 31;
    int mt = blockIdx.x, z = blockIdx.y;
    int m0 = mt * 128;
    int niter = 2 * (mt + 1);

    const __half* qhp = Qh + (size_t)z * Tt * HDP;
    const __half* qlp = Ql + (size_t)z * Tt * HDP;
    const __half* khp = Kh + (size_t)z * Tt * HDP;
    const __half* klp = Kl + (size_t)z * Tt * HDP;
    const __half* vtp = Vt + (size_t)z * HDim * Tt;

    #pragma unroll
    for (int u0 = 0; u0 < 16; u0++) {
        int u = u0 * 256 + tid;
        int hi = (u < 2048);
        int v = u & 2047;
        int row = v >> 4, c16 = v & 15;
        uint32_t dst = sb + (hi ? 0 : FQ_OP) + row * QROWB + c16 * 16;
        const __half* src = (hi ? qhp : qlp) + (size_t)(m0 + row) * HDP + c16 * 8;
        asm volatile("cp.async.cg.shared.global [%0], [%1], 16;" :: "r"(dst), "l"(src));
    }
    asm volatile("cp.async.commit_group;" ::: "memory");

    auto load_kv = [&](int i) {
        int k0 = i * 64;
        uint32_t st = sb + 2 * FQ_OP + (i & 1) * FSTGB;
        #pragma unroll
        for (int u0 = 0; u0 < 11; u0++) {
            int u = u0 * 256 + tid;
            if (u < 2048) {
                int hi = (u < 1024);
                int v = u & 1023;
                int row = v >> 4, c16 = v & 15;
                uint32_t dst = st + (hi ? 0 : FK_OP) + row * QROWB + c16 * 16;
                const __half* src = (hi ? khp : klp) + (size_t)(k0 + row) * HDP + c16 * 8;
                asm volatile("cp.async.cg.shared.global [%0], [%1], 16;" :: "r"(dst), "l"(src));
            } else {
                int v = u - 2048;
                int row = v >> 3, c16 = v & 7;
                uint32_t dst = st + 2 * FK_OP + row * VROWB + c16 * 16;
                const __half* src = vtp + (size_t)row * Tt + k0 + c16 * 8;
                asm volatile("cp.async.cg.shared.global [%0], [%1], 16;" :: "r"(dst), "l"(src));
            }
        }
        asm volatile("cp.async.commit_group;" ::: "memory");
    };

    load_kv(0);
    load_kv(1);

    float o[12][4] = {};
    float m_r = -1e30f, m_r8 = -1e30f, l_r = 0.f, l_r8 = 0.f;
    int qrow = m0 + wid * 16 + (lane >> 2);

    for (int i = 0; i < niter; i++) {
        if (i + 1 < niter) asm volatile("cp.async.wait_group 1;" ::: "memory");
        else               asm volatile("cp.async.wait_group 0;" ::: "memory");
        __syncthreads();
        uint32_t st = sb + 2 * FQ_OP + (i & 1) * FSTGB;
        int k0 = i * 64;

        float sacc[8][4] = {};
        uint32_t aqbase = sb + (uint32_t)(wid * 16 + (lane & 15)) * QROWB + (lane >> 4) * 16;
        uint32_t bkbase = st + (uint32_t)((lane & 7) + ((lane >> 4) & 1) * 8) * QROWB
                        + ((lane >> 3) & 1) * 16;
        #pragma unroll
        for (int kk = 0; kk < 8; kk++) {
            uint32_t ah[4], al[4];
            ldsm4(ah[0], ah[1], ah[2], ah[3], aqbase + kk * 32);
            ldsm4(al[0], al[1], al[2], al[3], aqbase + FQ_OP + kk * 32);
            #pragma unroll
            for (int np = 0; np < 4; np++) {
                uint32_t bh0[2], bh1[2], bl0[2], bl1[2];
                uint32_t bd = bkbase + np * (16 * QROWB) + kk * 32;
                ldsm4(bh0[0], bh0[1], bh1[0], bh1[1], bd);
                ldsm4(bl0[0], bl0[1], bl1[0], bl1[1], bd + FK_OP);
                mma16816(sacc[np*2],   ah, bh0);
                mma16816(sacc[np*2+1], ah, bh1);
                mma16816(sacc[np*2],   al, bh0);
                mma16816(sacc[np*2+1], al, bh1);
                mma16816(sacc[np*2],   ah, bl0);
                mma16816(sacc[np*2+1], ah, bl1);
            }
        }

        float tmax_r = -1e30f, tmax_r8 = -1e30f;
        #pragma unroll
        for (int t = 0; t < 8; t++) {
            #pragma unroll
            for (int jj = 0; jj < 2; jj++) {
                int kcol = k0 + t * 8 + (lane & 3) * 2 + jj;
                float s0 = (kcol <= qrow)     ? sacc[t][jj]     * ATT_SCALE : -1e30f;
                float s1 = (kcol <= qrow + 8) ? sacc[t][2 + jj] * ATT_SCALE : -1e30f;
                sacc[t][jj] = s0; sacc[t][2 + jj] = s1;
                tmax_r  = fmaxf(tmax_r, s0);
                tmax_r8 = fmaxf(tmax_r8, s1);
            }
        }
        tmax_r  = fmaxf(tmax_r,  __shfl_xor_sync(0xffffffffu, tmax_r, 1));
        tmax_r  = fmaxf(tmax_r,  __shfl_xor_sync(0xffffffffu, tmax_r, 2));
        tmax_r8 = fmaxf(tmax_r8, __shfl_xor_sync(0xffffffffu, tmax_r8, 1));
        tmax_r8 = fmaxf(tmax_r8, __shfl_xor_sync(0xffffffffu, tmax_r8, 2));
        float mn_r = fmaxf(m_r, tmax_r), mn_r8 = fmaxf(m_r8, tmax_r8);
        float f_r = __expf(m_r - mn_r), f_r8 = __expf(m_r8 - mn_r8);
        m_r = mn_r; m_r8 = mn_r8;

        uint32_t pr[8], pr8[8];
        float ls_r = 0.f, ls_r8 = 0.f;
        #pragma unroll
        for (int t = 0; t < 8; t++) {
            float p0 = __expf(sacc[t][0] - m_r);
            float p1 = __expf(sacc[t][1] - m_r);
            float p2 = __expf(sacc[t][2] - m_r8);
            float p3 = __expf(sacc[t][3] - m_r8);
            ls_r += p0 + p1; ls_r8 += p2 + p3;
            __half2 h01 = __floats2half2_rn(p0, p1);
            __half2 h23 = __floats2half2_rn(p2, p3);
            pr[t]  = *(uint32_t*)&h01;
            pr8[t] = *(uint32_t*)&h23;
        }
        ls_r  += __shfl_xor_sync(0xffffffffu, ls_r, 1);
        ls_r  += __shfl_xor_sync(0xffffffffu, ls_r, 2);
        ls_r8 += __shfl_xor_sync(0xffffffffu, ls_r8, 1);
        ls_r8 += __shfl_xor_sync(0xffffffffu, ls_r8, 2);
        l_r  = l_r  * f_r  + ls_r;
        l_r8 = l_r8 * f_r8 + ls_r8;
        #pragma unroll
        for (int t = 0; t < 12; t++) {
            o[t][0] *= f_r;  o[t][1] *= f_r;
            o[t][2] *= f_r8; o[t][3] *= f_r8;
        }

        uint32_t bvbase = st + 2 * FK_OP
                        + (uint32_t)((lane & 7) + ((lane >> 4) & 1) * 8) * VROWB
                        + ((lane >> 3) & 1) * 16;
        #pragma unroll
        for (int j = 0; j < 4; j++) {
            uint32_t a[4] = { pr[2*j], pr8[2*j], pr[2*j+1], pr8[2*j+1] };
            #pragma unroll
            for (int np = 0; np < 6; np++) {
                uint32_t bv0[2], bv1[2];
                ldsm4(bv0[0], bv0[1], bv1[0], bv1[1], bvbase + np * (16 * VROWB) + j * 32);
                mma16816(o[np*2],   a, bv0);
                mma16816(o[np*2+1], a, bv1);
            }
        }
        __syncthreads();
        if (i + 2 < niter) load_kv(i + 2);
    }

    float inv_r = 1.f / l_r, inv_r8 = 1.f / l_r8;
    int bb = z >> 3, h = z & 7;
    size_t base = (size_t)bb * Tt * Dd + (size_t)h * HDim;
    #pragma unroll
    for (int t = 0; t < 12; t++) {
        int n = t * 8 + (lane & 3) * 2;
        size_t ixr  = base + (size_t)qrow * Dd + n;
        size_t ixr8 = base + (size_t)(qrow + 8) * Dd + n;
        Oo[ixr]      = __float2half(o[t][0] * inv_r);
        Oo[ixr + 1]  = __float2half(o[t][1] * inv_r);
        Oo[ixr8]     = __float2half(o[t][2] * inv_r8);
        Oo[ixr8 + 1] = __float2half(o[t][3] * inv_r8);
    }
}

// ---------------- launch ----------------
extern "C" void kernel_launch(void* const* d_in, const int* in_sizes, int n_in,
                              void* d_out, int out_size) {
    const int*   idx    = (const int*)  d_in[0];
    const float* tok    = (const float*)d_in[1];
    const float* pos    = (const float*)d_in[2];
    const float* ln1_s  = (const float*)d_in[3];
    const float* ln1_b  = (const float*)d_in[4];
    const float* qkv_w  = (const float*)d_in[5];
    const float* out_w  = (const float*)d_in[6];
    const float* ln2_s  = (const float*)d_in[7];
    const float* ln2_b  = (const float*)d_in[8];
    const float* ffn_w1 = (const float*)d_in[9];
    const float* ffn_b1 = (const float*)d_in[10];
    const float* ffn_w2 = (const float*)d_in[11];
    const float* ffn_b2 = (const float*)d_in[12];
    const float* fn_s   = (const float*)d_in[13];
    const float* fn_b   = (const float*)d_in[14];
    const float* head_w = (const float*)d_in[15];

    float* logits = (float*)d_out;
    float* hidden = logits + (size_t)Bz * Tt * Vv;

    float *x;
    __half *h16, *f16, *qh, *ql, *kh, *kl, *vth, *oh;
    __half *wq, *wo, *w1, *w2, *wh;
    cudaGetSymbolAddress((void**)&x,   g_x);
    cudaGetSymbolAddress((void**)&h16, g_h16);
    cudaGetSymbolAddress((void**)&f16, g_f16);
    cudaGetSymbolAddress((void**)&qh,  g_qh);  cudaGetSymbolAddress((void**)&ql, g_ql);
    cudaGetSymbolAddress((void**)&kh,  g_kh);  cudaGetSymbolAddress((void**)&kl, g_kl);
    cudaGetSymbolAddress((void**)&vth, g_vth);
    cudaGetSymbolAddress((void**)&oh,  g_oh);
    cudaGetSymbolAddress((void**)&wq,  g_wq);
    cudaGetSymbolAddress((void**)&wo,  g_wo);
    cudaGetSymbolAddress((void**)&w1,  g_w1);
    cudaGetSymbolAddress((void**)&w2,  g_w2);
    cudaGetSymbolAddress((void**)&wh,  g_wh);

    cudaFuncSetAttribute((const void*)gemm_mm<4,2>, cudaFuncAttributeMaxDynamicSharedMemorySize, SMEM_MM4);
    cudaFuncSetAttribute((const void*)gemm_mm<8,1>, cudaFuncAttributeMaxDynamicSharedMemorySize, SMEM_MM8);
    cudaFuncSetAttribute(flash_attn, cudaFuncAttributeMaxDynamicSharedMemorySize, SMEM_FA);

    size_t n1 = (size_t)Ll * 3 * Dd * Dd / 4;
    size_t n2 = (size_t)Ll * Dd * Dd / 4;
    size_t n3 = (size_t)Ll * 4 * Dd * Dd / 4;
    size_t n5 = (size_t)Vv * Dd / 4;

    // launch order: cvt_wq, embed, ln, qkv-gemm FIRST so the fixed ncu capture
    // slot lands on ln_k / gemm_mm instead of a cvt kernel.
    cvt_k<<<(unsigned)((n1 + 255) / 256), 256>>>(qkv_w,  wq, n1);
    embed_k<<<(MR * Dd) / 256, 256>>>(idx, tok, pos, x);
    ln_k<<<MR, 256>>>(x, ln1_s, ln1_b, h16, nullptr);
    gemm_mm<8,1><<<dim3(9, 16), 256, SMEM_MM8>>>(h16, wq, 3 * Dd, Dd,
                                                 nullptr, nullptr, nullptr, nullptr, 2, 0);
    cvt_k<<<(unsigned)((n2 + 255) / 256), 256>>>(out_w,  wo, n2);
    cvt_k<<<(unsigned)((n3 + 255) / 256), 256>>>(ffn_w1, w1, n3);
    cvt_k<<<(unsigned)((n3 + 255) / 256), 256>>>(ffn_w2, w2, n3);
    cvt_k<<<(unsigned)((n5 + 255) / 256), 256>>>(head_w, wh, n5);

    for (int l = 0; l < Ll; l++) {
        if (l > 0) {
            ln_k<<<MR, 256>>>(x, ln1_s + l * Dd, ln1_b + l * Dd, h16, nullptr);
            gemm_mm<8,1><<<dim3(9, 16), 256, SMEM_MM8>>>(h16, wq + (size_t)l * 3 * Dd * Dd,
                                                         3 * Dd, Dd, nullptr, nullptr,
                                                         nullptr, nullptr, 2, 0);
        }
        flash_attn<<<dim3(4, BH), 256, SMEM_FA>>>(qh, ql, kh, kl, vth, oh);
        gemm_mm<4,2><<<dim3(6, 16), 256, SMEM_MM4>>>(oh, wo + (size_t)l * Dd * Dd,
                                                     Dd, Dd, nullptr, x, x, nullptr, 0, 0);
        ln_k<<<MR, 256>>>(x, ln2_s + l * Dd, ln2_b + l * Dd, h16, nullptr);
        gemm_mm<8,1><<<dim3(12, 16), 256, SMEM_MM8>>>(h16, w1 + (size_t)l * 4 * Dd * Dd,
                                                      4 * Dd, Dd, ffn_b1 + l * 4 * Dd, nullptr,
                                                      nullptr, f16, 1, 0);
        gemm_mm<4,2><<<dim3(6, 16), 256, SMEM_MM4>>>(f16, w2 + (size_t)l * 4 * Dd * Dd,
                                                     Dd, 4 * Dd, ffn_b2 + l * Dd, x, x, nullptr, 0, 0);
    }

    ln_k<<<MR, 256>>>(x, fn_s, fn_b, h16, hidden);
    // head GEMM: swapxy=1 so a scheduling wave shares weight tiles (B streamed once)
    gemm_mm<8,1><<<dim3(16, 197), 256, SMEM_MM8>>>(h16, wh, Vv, Dd,
                                                   nullptr, nullptr, logits, nullptr, 0, 1);
}

// round 14
// speedup vs baseline: 1.0005x; 1.0005x over previous
#include <cuda_runtime.h>
#include <cuda_fp16.h>
#include <math.h>
#include <stdint.h>

#define Bz   4
#define Tt   512
#define Dd   768
#define Hh   8
#define HDim 96
#define HDP  128            // padded head dim for MMA (pad cols stay zero: globals zero-init)
#define Ll   12
#define Vv   50257
#define MR   (Bz*Tt)
#define BH   (Bz*Hh)
#define ATT_SCALE 0.10206207261596575f

__device__ __forceinline__ uint32_t smem_u32(const void* p) {
    uint32_t a;
    asm("{ .reg .u64 t; cvta.to.shared.u64 t, %1; cvt.u32.u64 %0, t; }" : "=r"(a) : "l"(p));
    return a;
}

// ---------------- scratch (device globals) ----------------
__device__ float g_x [MR*Dd];
__device__ __align__(16) __half g_h16[MR*Dd];
__device__ __align__(16) __half g_f16[MR*4*Dd];
__device__ __align__(16) __half g_qh[(size_t)BH*Tt*HDP], g_ql[(size_t)BH*Tt*HDP];
__device__ __align__(16) __half g_kh[(size_t)BH*Tt*HDP], g_kl[(size_t)BH*Tt*HDP];
__device__ __align__(16) __half g_vth[(size_t)BH*HDim*Tt];
__device__ __align__(16) __half g_oh[MR*Dd];
__device__ __align__(16) __half g_wq[(size_t)Ll*3*Dd*Dd];
__device__ __align__(16) __half g_wo[(size_t)Ll*Dd*Dd];
__device__ __align__(16) __half g_w1[(size_t)Ll*4*Dd*Dd];
__device__ __align__(16) __half g_w2[(size_t)Ll*4*Dd*Dd];
__device__ __align__(16) __half g_wh[(size_t)Vv*Dd];

// ---------------- weight fp32 -> fp16 ----------------
__global__ void cvt_k(const float* __restrict__ w, __half* __restrict__ o, size_t n4) {
    size_t i = (size_t)blockIdx.x * 256 + threadIdx.x;
    if (i >= n4) return;
    float4 v = ((const float4*)w)[i];
    ((__half2*)o)[i * 2]     = __floats2half2_rn(v.x, v.y);
    ((__half2*)o)[i * 2 + 1] = __floats2half2_rn(v.z, v.w);
}

// ---------------- embedding ----------------
__global__ void embed_k(const int* __restrict__ idx, const float* __restrict__ tok,
                        const float* __restrict__ pos, float* __restrict__ x) {
    int i = blockIdx.x * 256 + threadIdx.x;
    int m = i / Dd, d = i - m * Dd;
    int t = m & (Tt - 1);
    x[i] = tok[(size_t)idx[m] * Dd + d] + pos[t * Dd + d];
}

// ---------------- layernorm -> fp16 (+ optional fp32) ----------------
__global__ void ln_k(const float* __restrict__ in, const float* __restrict__ s,
                     const float* __restrict__ b, __half* __restrict__ oh,
                     float* __restrict__ ofp) {
    int m = blockIdx.x, tid = threadIdx.x;
    const float* row = in + (size_t)m * Dd;
    float x0 = row[tid], x1 = row[tid + 256], x2 = row[tid + 512];
    __shared__ float red[256];
    red[tid] = x0 + x1 + x2;
    __syncthreads();
    #pragma unroll
    for (int st = 128; st > 0; st >>= 1) { if (tid < st) red[tid] += red[tid + st]; __syncthreads(); }
    float mean = red[0] * (1.0f / Dd);
    __syncthreads();
    float d0 = x0 - mean, d1 = x1 - mean, d2 = x2 - mean;
    red[tid] = d0 * d0 + d1 * d1 + d2 * d2;
    __syncthreads();
    #pragma unroll
    for (int st = 128; st > 0; st >>= 1) { if (tid < st) red[tid] += red[tid + st]; __syncthreads(); }
    float inv = rsqrtf(red[0] * (1.0f / Dd) + 1e-5f);
    size_t base = (size_t)m * Dd;
    #pragma unroll
    for (int q = 0; q < 3; q++) {
        int c = tid + q * 256;
        float dv = (q == 0 ? d0 : (q == 1 ? d1 : d2));
        float v = dv * inv * s[c] + b[c];
        oh[base + c] = __float2half(v);
        if (ofp) ofp[base + c] = v;
    }
}

// ---------------- HMMA primitives ----------------
__device__ __forceinline__ void ldsm4(uint32_t& r0, uint32_t& r1, uint32_t& r2, uint32_t& r3,
                                      uint32_t addr) {
    asm volatile("ldmatrix.sync.aligned.m8n8.x4.shared.b16 {%0,%1,%2,%3}, [%4];"
                 : "=r"(r0), "=r"(r1), "=r"(r2), "=r"(r3) : "r"(addr));
}
__device__ __forceinline__ void mma16816(float* d, const uint32_t* a, const uint32_t* b) {
    asm volatile("mma.sync.aligned.m16n8k16.row.col.f32.f16.f16.f32 "
                 "{%0,%1,%2,%3}, {%4,%5,%6,%7}, {%8,%9}, {%0,%1,%2,%3};"
                 : "+f"(d[0]), "+f"(d[1]), "+f"(d[2]), "+f"(d[3])
                 : "r"(a[0]), "r"(a[1]), "r"(a[2]), "r"(a[3]), "r"(b[0]), "r"(b[1]));
}

#define ROWB 144

// ---------------- templated fp16 GEMM: C[M,N] = A[M,K]*B[N,K]^T, fp32 acc ------
// CTA tile 128 x (NT*32); 8 warps as 2x4; warp tile 64 x (NT*8). K-chunk 64,
// cp.async double buffer. mode: 0 normal | 1 gelu(bias) | 2 qkv split scatter.
// swapxy: m from blockIdx.x (fast) -> concurrent CTAs share B tiles.
template<int NT, int MINB>
__global__ __launch_bounds__(256, MINB) void gemm_mm(
    const __half* __restrict__ A, const __half* __restrict__ Bm,
    int N, int K,
    const float* __restrict__ bias, const float* __restrict__ resid,
    float* __restrict__ Cf, __half* __restrict__ Ch, int mode, int swapxy)
{
    constexpr int CTA_N = NT * 32;
    constexpr int OPB_A = 128 * ROWB;
    constexpr int OPB_B = CTA_N * ROWB;
    constexpr int STGT  = OPB_A + OPB_B;
    constexpr int NXFER = (128 + CTA_N) * 8;      // 16B transfers per chunk

    extern __shared__ char smem[];
    uint32_t sb = smem_u32(smem);
    int tid = threadIdx.x, wid = tid >> 5, lane = tid & 31;
    int wm = wid >> 2, wn = wid & 3;
    int m0 = (swapxy ? blockIdx.x : blockIdx.y) * 128;
    int n0 = (swapxy ? blockIdx.y : blockIdx.x) * CTA_N;

    auto load_chunk = [&](int c) {
        int kt = c << 6;
        uint32_t st = sb + (c & 1) * STGT;
        #pragma unroll
        for (int o = 0; o < NXFER / 256; o++) {
            int flat = o * 256 + tid;
            uint32_t dst;
            const __half* src;
            if (flat < 1024) {                    // A: 128 rows x 8
                int row = flat >> 3, c16 = flat & 7;
                dst = st + row * ROWB + c16 * 16;
                src = A + (size_t)(m0 + row) * K + kt + c16 * 8;
            } else {                              // B: CTA_N rows x 8
                int v = flat - 1024;
                int row = v >> 3, c16 = v & 7;
                dst = st + OPB_A + row * ROWB + c16 * 16;
                int r = n0 + row; if (r >= N) r = N - 1;
                src = Bm + (size_t)r * K + kt + c16 * 8;
            }
            asm volatile("cp.async.cg.shared.global [%0], [%1], 16;" :: "r"(dst), "l"(src));
        }
        asm volatile("cp.async.commit_group;" ::: "memory");
    };

    float acc[4][NT][4] = {};
    int nc = K >> 6;

    load_chunk(0);
    load_chunk(1);

    for (int c = 0; c < nc; c++) {
        if (c + 1 < nc) asm volatile("cp.async.wait_group 1;" ::: "memory");
        else            asm volatile("cp.async.wait_group 0;" ::: "memory");
        __syncthreads();
        uint32_t st = sb + (c & 1) * STGT;
        uint32_t a_row = (uint32_t)(wm * 64 + (lane & 15)) * ROWB + (lane >> 4) * 16;
        uint32_t b_row = (uint32_t)(wn * CTA_N / 4 + (lane & 7) + ((lane >> 4) & 1) * 8) * ROWB
                       + ((lane >> 3) & 1) * 16;
        #pragma unroll
        for (int kk = 0; kk < 4; kk++) {
            uint32_t ah[4][4], bh[NT][2];
            #pragma unroll
            for (int mt = 0; mt < 4; mt++) {
                uint32_t ad = st + a_row + mt * (16 * ROWB) + kk * 32;
                ldsm4(ah[mt][0], ah[mt][1], ah[mt][2], ah[mt][3], ad);
            }
            #pragma unroll
            for (int np = 0; np < NT / 2; np++) {
                uint32_t bd = st + OPB_A + b_row + np * (16 * ROWB) + kk * 32;
                ldsm4(bh[np*2][0], bh[np*2][1], bh[np*2+1][0], bh[np*2+1][1], bd);
            }
            #pragma unroll
            for (int mt = 0; mt < 4; mt++)
                #pragma unroll
                for (int nt = 0; nt < NT; nt++)
                    mma16816(acc[mt][nt], ah[mt], bh[nt]);
        }
        __syncthreads();
        if (c + 2 < nc) load_chunk(c + 2);
    }

    #pragma unroll
    for (int mt = 0; mt < 4; mt++) {
        #pragma unroll
        for (int nt = 0; nt < NT; nt++) {
            int mbase = m0 + wm * 64 + mt * 16 + (lane >> 2);
            int nbase = n0 + wn * (NT * 8) + nt * 8 + (lane & 3) * 2;
            #pragma unroll
            for (int hrow = 0; hrow < 2; hrow++) {
                int m = mbase + hrow * 8;
                #pragma unroll
                for (int jj = 0; jj < 2; jj++) {
                    int n = nbase + jj;
                    float v = acc[mt][nt][hrow * 2 + jj];
                    if (mode == 2) {
                        int sct = n / Dd, r = n - sct * Dd;
                        int h = r / HDim, hd = r - h * HDim;
                        int bb = m >> 9, t = m & (Tt - 1);
                        int bh_ = bb * Hh + h;
                        if (sct == 0) {
                            size_t ix = ((size_t)bh_ * Tt + t) * HDP + hd;
                            __half hv = __float2half(v);
                            g_qh[ix] = hv;
                            g_ql[ix] = __float2half(v - __half2float(hv));
                        } else if (sct == 1) {
                            size_t ix = ((size_t)bh_ * Tt + t) * HDP + hd;
                            __half hv = __float2half(v);
                            g_kh[ix] = hv;
                            g_kl[ix] = __float2half(v - __half2float(hv));
                        } else {
                            g_vth[((size_t)bh_ * HDim + hd) * Tt + t] = __float2half(v);
                        }
                    } else if (n < N) {
                        if (bias) v += bias[n];
                        if (mode == 1) v = 0.5f * v * (1.0f + erff(v * 0.70710678118654752f));
                        size_t ix = (size_t)m * N + n;
                        if (resid) v += resid[ix];
                        if (Cf) Cf[ix] = v;
                        if (Ch) Ch[ix] = __float2half(v);
                    }
                }
            }
        }
    }
}

#define SMEM_MM4 (2*(128+128)*ROWB)   // 73728
#define SMEM_MM8 (2*(128+256)*ROWB)   // 110592

// ---------------- fused flash attention (proven in R10; unchanged) ----------------
#define QROWB 272
#define VROWB 144
#define FQ_OP (128*QROWB)
#define FK_OP (64*QROWB)
#define FV_OP (96*VROWB)
#define FSTGB (2*FK_OP + FV_OP)
#define SMEM_FA (2*FQ_OP + 2*FSTGB)  // 166912

__global__ __launch_bounds__(256, 1) void flash_attn(
    const __half* __restrict__ Qh, const __half* __restrict__ Ql,
    const __half* __restrict__ Kh, const __half* __restrict__ Kl,
    const __half* __restrict__ Vt, __half* __restrict__ Oo)
{
    extern __shared__ char smem[];
    uint32_t sb = smem_u32(smem);
    int tid = threadIdx.x, wid = tid >> 5, lane = tid & 31;
    int mt = blockIdx.x, z = blockIdx.y;
    int m0 = mt * 128;
    int niter = 2 * (mt + 1);

    const __half* qhp = Qh + (size_t)z * Tt * HDP;
    const __half* qlp = Ql + (size_t)z * Tt * HDP;
    const __half* khp = Kh + (size_t)z * Tt * HDP;
    const __half* klp = Kl + (size_t)z * Tt * HDP;
    const __half* vtp = Vt + (size_t)z * HDim * Tt;

    #pragma unroll
    for (int u0 = 0; u0 < 16; u0++) {
        int u = u0 * 256 + tid;
        int hi = (u < 2048);
        int v = u & 2047;
        int row = v >> 4, c16 = v & 15;
        uint32_t dst = sb + (hi ? 0 : FQ_OP) + row * QROWB + c16 * 16;
        const __half* src = (hi ? qhp : qlp) + (size_t)(m0 + row) * HDP + c16 * 8;
        asm volatile("cp.async.cg.shared.global [%0], [%1], 16;" :: "r"(dst), "l"(src));
    }
    asm volatile("cp.async.commit_group;" ::: "memory");

    auto load_kv = [&](int i) {
        int k0 = i * 64;
        uint32_t st = sb + 2 * FQ_OP + (i & 1) * FSTGB;
        #pragma unroll
        for (int u0 = 0; u0 < 11; u0++) {
            int u = u0 * 256 + tid;
            if (u < 2048) {
                int hi = (u < 1024);
                int v = u & 1023;
                int row = v >> 4, c16 = v & 15;
                uint32_t dst = st + (hi ? 0 : FK_OP) + row * QROWB + c16 * 16;
                const __half* src = (hi ? khp : klp) + (size_t)(k0 + row) * HDP + c16 * 8;
                asm volatile("cp.async.cg.shared.global [%0], [%1], 16;" :: "r"(dst), "l"(src));
            } else {
                int v = u - 2048;
                int row = v >> 3, c16 = v & 7;
                uint32_t dst = st + 2 * FK_OP + row * VROWB + c16 * 16;
                const __half* src = vtp + (size_t)row * Tt + k0 + c16 * 8;
                asm volatile("cp.async.cg.shared.global [%0], [%1], 16;" :: "r"(dst), "l"(src));
            }
        }
        asm volatile("cp.async.commit_group;" ::: "memory");
    };

    load_kv(0);
    load_kv(1);

    float o[12][4] = {};
    float m_r = -1e30f, m_r8 = -1e30f, l_r = 0.f, l_r8 = 0.f;
    int qrow = m0 + wid * 16 + (lane >> 2);

    for (int i = 0; i < niter; i++) {
        if (i + 1 < niter) asm volatile("cp.async.wait_group 1;" ::: "memory");
        else               asm volatile("cp.async.wait_group 0;" ::: "memory");
        __syncthreads();
        uint32_t st = sb + 2 * FQ_OP + (i & 1) * FSTGB;
        int k0 = i * 64;

        float sacc[8][4] = {};
        uint32_t aqbase = sb + (uint32_t)(wid * 16 + (lane & 15)) * QROWB + (lane >> 4) * 16;
        uint32_t bkbase = st + (uint32_t)((lane & 7) + ((lane >> 4) & 1) * 8) * QROWB
                        + ((lane >> 3) & 1) * 16;
        #pragma unroll
        for (int kk = 0; kk < 8; kk++) {
            uint32_t ah[4], al[4];
            ldsm4(ah[0], ah[1], ah[2], ah[3], aqbase + kk * 32);
            ldsm4(al[0], al[1], al[2], al[3], aqbase + FQ_OP + kk * 32);
            #pragma unroll
            for (int np = 0; np < 4; np++) {
                uint32_t bh0[2], bh1[2], bl0[2], bl1[2];
                uint32_t bd = bkbase + np * (16 * QROWB) + kk * 32;
                ldsm4(bh0[0], bh0[1], bh1[0], bh1[1], bd);
                ldsm4(bl0[0], bl0[1], bl1[0], bl1[1], bd + FK_OP);
                mma16816(sacc[np*2],   ah, bh0);
                mma16816(sacc[np*2+1], ah, bh1);
                mma16816(sacc[np*2],   al, bh0);
                mma16816(sacc[np*2+1], al, bh1);
                mma16816(sacc[np*2],   ah, bl0);
                mma16816(sacc[np*2+1], ah, bl1);
            }
        }

        float tmax_r = -1e30f, tmax_r8 = -1e30f;
        #pragma unroll
        for (int t = 0; t < 8; t++) {
            #pragma unroll
            for (int jj = 0; jj < 2; jj++) {
                int kcol = k0 + t * 8 + (lane & 3) * 2 + jj;
                float s0 = (kcol <= qrow)     ? sacc[t][jj]     * ATT_SCALE : -1e30f;
                float s1 = (kcol <= qrow + 8) ? sacc[t][2 + jj] * ATT_SCALE : -1e30f;
                sacc[t][jj] = s0; sacc[t][2 + jj] = s1;
                tmax_r  = fmaxf(tmax_r, s0);
                tmax_r8 = fmaxf(tmax_r8, s1);
            }
        }
        tmax_r  = fmaxf(tmax_r,  __shfl_xor_sync(0xffffffffu, tmax_r, 1));
        tmax_r  = fmaxf(tmax_r,  __shfl_xor_sync(0xffffffffu, tmax_r, 2));
        tmax_r8 = fmaxf(tmax_r8, __shfl_xor_sync(0xffffffffu, tmax_r8, 1));
        tmax_r8 = fmaxf(tmax_r8, __shfl_xor_sync(0xffffffffu, tmax_r8, 2));
        float mn_r = fmaxf(m_r, tmax_r), mn_r8 = fmaxf(m_r8, tmax_r8);
        float f_r = __expf(m_r - mn_r), f_r8 = __expf(m_r8 - mn_r8);
        m_r = mn_r; m_r8 = mn_r8;

        uint32_t pr[8], pr8[8];
        float ls_r = 0.f, ls_r8 = 0.f;
        #pragma unroll
        for (int t = 0; t < 8; t++) {
            float p0 = __expf(sacc[t][0] - m_r);
            float p1 = __expf(sacc[t][1] - m_r);
            float p2 = __expf(sacc[t][2] - m_r8);
            float p3 = __expf(sacc[t][3] - m_r8);
            ls_r += p0 + p1; ls_r8 += p2 + p3;
            __half2 h01 = __floats2half2_rn(p0, p1);
            __half2 h23 = __floats2half2_rn(p2, p3);
            pr[t]  = *(uint32_t*)&h01;
            pr8[t] = *(uint32_t*)&h23;
        }
        ls_r  += __shfl_xor_sync(0xffffffffu, ls_r, 1);
        ls_r  += __shfl_xor_sync(0xffffffffu, ls_r, 2);
        ls_r8 += __shfl_xor_sync(0xffffffffu, ls_r8, 1);
        ls_r8 += __shfl_xor_sync(0xffffffffu, ls_r8, 2);
        l_r  = l_r  * f_r  + ls_r;
        l_r8 = l_r8 * f_r8 + ls_r8;
        #pragma unroll
        for (int t = 0; t < 12; t++) {
            o[t][0] *= f_r;  o[t][1] *= f_r;
            o[t][2] *= f_r8; o[t][3] *= f_r8;
        }

        uint32_t bvbase = st + 2 * FK_OP
                        + (uint32_t)((lane & 7) + ((lane >> 4) & 1) * 8) * VROWB
                        + ((lane >> 3) & 1) * 16;
        #pragma unroll
        for (int j = 0; j < 4; j++) {
            uint32_t a[4] = { pr[2*j], pr8[2*j], pr[2*j+1], pr8[2*j+1] };
            #pragma unroll
            for (int np = 0; np < 6; np++) {
                uint32_t bv0[2], bv1[2];
                ldsm4(bv0[0], bv0[1], bv1[0], bv1[1], bvbase + np * (16 * VROWB) + j * 32);
                mma16816(o[np*2],   a, bv0);
                mma16816(o[np*2+1], a, bv1);
            }
        }
        __syncthreads();
        if (i + 2 < niter) load_kv(i + 2);
    }

    float inv_r = 1.f / l_r, inv_r8 = 1.f / l_r8;
    int bb = z >> 3, h = z & 7;
    size_t base = (size_t)bb * Tt * Dd + (size_t)h * HDim;
    #pragma unroll
    for (int t = 0; t < 12; t++) {
        int n = t * 8 + (lane & 3) * 2;
        size_t ixr  = base + (size_t)qrow * Dd + n;
        size_t ixr8 = base + (size_t)(qrow + 8) * Dd + n;
        Oo[ixr]      = __float2half(o[t][0] * inv_r);
        Oo[ixr + 1]  = __float2half(o[t][1] * inv_r);
        Oo[ixr8]     = __float2half(o[t][2] * inv_r8);
        Oo[ixr8 + 1] = __float2half(o[t][3] * inv_r8);
    }
}

// ---------------- launch ----------------
extern "C" void kernel_launch(void* const* d_in, const int* in_sizes, int n_in,
                              void* d_out, int out_size) {
    const int*   idx    = (const int*)  d_in[0];
    const float* tok    = (const float*)d_in[1];
    const float* pos    = (const float*)d_in[2];
    const float* ln1_s  = (const float*)d_in[3];
    const float* ln1_b  = (const float*)d_in[4];
    const float* qkv_w  = (const float*)d_in[5];
    const float* out_w  = (const float*)d_in[6];
    const float* ln2_s  = (const float*)d_in[7];
    const float* ln2_b  = (const float*)d_in[8];
    const float* ffn_w1 = (const float*)d_in[9];
    const float* ffn_b1 = (const float*)d_in[10];
    const float* ffn_w2 = (const float*)d_in[11];
    const float* ffn_b2 = (const float*)d_in[12];
    const float* fn_s   = (const float*)d_in[13];
    const float* fn_b   = (const float*)d_in[14];
    const float* head_w = (const float*)d_in[15];

    float* logits = (float*)d_out;
    float* hidden = logits + (size_t)Bz * Tt * Vv;

    float *x;
    __half *h16, *f16, *qh, *ql, *kh, *kl, *vth, *oh;
    __half *wq, *wo, *w1, *w2, *wh;
    cudaGetSymbolAddress((void**)&x,   g_x);
    cudaGetSymbolAddress((void**)&h16, g_h16);
    cudaGetSymbolAddress((void**)&f16, g_f16);
    cudaGetSymbolAddress((void**)&qh,  g_qh);  cudaGetSymbolAddress((void**)&ql, g_ql);
    cudaGetSymbolAddress((void**)&kh,  g_kh);  cudaGetSymbolAddress((void**)&kl, g_kl);
    cudaGetSymbolAddress((void**)&vth, g_vth);
    cudaGetSymbolAddress((void**)&oh,  g_oh);
    cudaGetSymbolAddress((void**)&wq,  g_wq);
    cudaGetSymbolAddress((void**)&wo,  g_wo);
    cudaGetSymbolAddress((void**)&w1,  g_w1);
    cudaGetSymbolAddress((void**)&w2,  g_w2);
    cudaGetSymbolAddress((void**)&wh,  g_wh);

    cudaFuncSetAttribute((const void*)gemm_mm<4,2>, cudaFuncAttributeMaxDynamicSharedMemorySize, SMEM_MM4);
    cudaFuncSetAttribute((const void*)gemm_mm<8,1>, cudaFuncAttributeMaxDynamicSharedMemorySize, SMEM_MM8);
    cudaFuncSetAttribute(flash_attn, cudaFuncAttributeMaxDynamicSharedMemorySize, SMEM_FA);

    size_t n1 = (size_t)Ll * 3 * Dd * Dd / 4;
    size_t n2 = (size_t)Ll * Dd * Dd / 4;
    size_t n3 = (size_t)Ll * 4 * Dd * Dd / 4;
    size_t n5 = (size_t)Vv * Dd / 4;

    // launch order: cvt_wq, embed, ln, qkv-gemm FIRST so the fixed ncu capture
    // slot lands on ln_k / gemm_mm instead of a cvt kernel.
    cvt_k<<<(unsigned)((n1 + 255) / 256), 256>>>(qkv_w,  wq, n1);
    embed_k<<<(MR * Dd) / 256, 256>>>(idx, tok, pos, x);
    ln_k<<<MR, 256>>>(x, ln1_s, ln1_b, h16, nullptr);
    gemm_mm<8,1><<<dim3(9, 16), 256, SMEM_MM8>>>(h16, wq, 3 * Dd, Dd,
                                                 nullptr, nullptr, nullptr, nullptr, 2, 0);
    cvt_k<<<(unsigned)((n2 + 255) / 256), 256>>>(out_w,  wo, n2);
    cvt_k<<<(unsigned)((n3 + 255) / 256), 256>>>(ffn_w1, w1, n3);
    cvt_k<<<(unsigned)((n3 + 255) / 256), 256>>>(ffn_w2, w2, n3);
    cvt_k<<<(unsigned)((n5 + 255) / 256), 256>>>(head_w, wh, n5);

    for (int l = 0; l < Ll; l++) {
        if (l > 0) {
            ln_k<<<MR, 256>>>(x, ln1_s + l * Dd, ln1_b + l * Dd, h16, nullptr);
            gemm_mm<8,1><<<dim3(9, 16), 256, SMEM_MM8>>>(h16, wq + (size_t)l * 3 * Dd * Dd,
                                                         3 * Dd, Dd, nullptr, nullptr,
                                                         nullptr, nullptr, 2, 0);
        }
        flash_attn<<<dim3(4, BH), 256, SMEM_FA>>>(qh, ql, kh, kl, vth, oh);
        gemm_mm<4,2><<<dim3(6, 16), 256, SMEM_MM4>>>(oh, wo + (size_t)l * Dd * Dd,
                                                     Dd, Dd, nullptr, x, x, nullptr, 0, 0);
        ln_k<<<MR, 256>>>(x, ln2_s + l * Dd, ln2_b + l * Dd, h16, nullptr);
        gemm_mm<8,1><<<dim3(12, 16), 256, SMEM_MM8>>>(h16, w1 + (size_t)l * 4 * Dd * Dd,
                                                      4 * Dd, Dd, ffn_b1 + l * 4 * Dd, nullptr,
                                                      nullptr, f16, 1, 0);
        gemm_mm<4,2><<<dim3(6, 16), 256, SMEM_MM4>>>(f16, w2 + (size_t)l * 4 * Dd * Dd,
                                                     Dd, 4 * Dd, ffn_b2 + l * Dd, x, x, nullptr, 0, 0);
    }

    ln_k<<<MR, 256>>>(x, fn_s, fn_b, h16, hidden);
    // head GEMM: swapxy=1 so a scheduling wave shares weight tiles (B streamed once)
    gemm_mm<8,1><<<dim3(16, 197), 256, SMEM_MM8>>>(h16, wh, Vv, Dd,
                                                   nullptr, nullptr, logits, nullptr, 0, 1);
}

// round 15
// speedup vs baseline: 2.8541x; 2.8526x over previous
#include <cuda_runtime.h>
#include <cuda_fp16.h>
#include <math.h>
#include <stdint.h>

#define Bz   4
#define Tt   512
#define Dd   768
#define Hh   8
#define HDim 96
#define HDP  128            // padded head dim for MMA (pad cols stay zero: globals zero-init)
#define Ll   12
#define Vv   50257
#define MR   (Bz*Tt)
#define BH   (Bz*Hh)
#define ATT_SCALE 0.10206207261596575f

__device__ __forceinline__ uint32_t smem_u32(const void* p) {
    uint32_t a;
    asm("{ .reg .u64 t; cvta.to.shared.u64 t, %1; cvt.u32.u64 %0, t; }" : "=r"(a) : "l"(p));
    return a;
}

// ---------------- scratch (device globals) ----------------
__device__ float g_x [MR*Dd];
__device__ __align__(16) __half g_h16[MR*Dd];
__device__ __align__(16) __half g_f16[MR*4*Dd];
__device__ __align__(16) __half g_qh[(size_t)BH*Tt*HDP], g_ql[(size_t)BH*Tt*HDP];
__device__ __align__(16) __half g_kh[(size_t)BH*Tt*HDP], g_kl[(size_t)BH*Tt*HDP];
__device__ __align__(16) __half g_vth[(size_t)BH*HDim*Tt];
__device__ __align__(16) __half g_oh[MR*Dd];
__device__ __align__(16) __half g_wq[(size_t)Ll*3*Dd*Dd];
__device__ __align__(16) __half g_wo[(size_t)Ll*Dd*Dd];
__device__ __align__(16) __half g_w1[(size_t)Ll*4*Dd*Dd];
__device__ __align__(16) __half g_w2[(size_t)Ll*4*Dd*Dd];
__device__ __align__(16) __half g_wh[(size_t)Vv*Dd];

// ---------------- weight fp32 -> fp16 ----------------
__global__ void cvt_k(const float* __restrict__ w, __half* __restrict__ o, size_t n4) {
    size_t i = (size_t)blockIdx.x * 256 + threadIdx.x;
    if (i >= n4) return;
    float4 v = ((const float4*)w)[i];
    ((__half2*)o)[i * 2]     = __floats2half2_rn(v.x, v.y);
    ((__half2*)o)[i * 2 + 1] = __floats2half2_rn(v.z, v.w);
}

// ---------------- embedding ----------------
__global__ void embed_k(const int* __restrict__ idx, const float* __restrict__ tok,
                        const float* __restrict__ pos, float* __restrict__ x) {
    int i = blockIdx.x * 256 + threadIdx.x;
    int m = i / Dd, d = i - m * Dd;
    int t = m & (Tt - 1);
    x[i] = tok[(size_t)idx[m] * Dd + d] + pos[t * Dd + d];
}

// ---------------- layernorm -> fp16 (+ optional fp32) ----------------
__global__ void ln_k(const float* __restrict__ in, const float* __restrict__ s,
                     const float* __restrict__ b, __half* __restrict__ oh,
                     float* __restrict__ ofp) {
    int m = blockIdx.x, tid = threadIdx.x;
    const float* row = in + (size_t)m * Dd;
    float x0 = row[tid], x1 = row[tid + 256], x2 = row[tid + 512];
    __shared__ float red[256];
    red[tid] = x0 + x1 + x2;
    __syncthreads();
    #pragma unroll
    for (int st = 128; st > 0; st >>= 1) { if (tid < st) red[tid] += red[tid + st]; __syncthreads(); }
    float mean = red[0] * (1.0f / Dd);
    __syncthreads();
    float d0 = x0 - mean, d1 = x1 - mean, d2 = x2 - mean;
    red[tid] = d0 * d0 + d1 * d1 + d2 * d2;
    __syncthreads();
    #pragma unroll
    for (int st = 128; st > 0; st >>= 1) { if (tid < st) red[tid] += red[tid + st]; __syncthreads(); }
    float inv = rsqrtf(red[0] * (1.0f / Dd) + 1e-5f);
    size_t base = (size_t)m * Dd;
    #pragma unroll
    for (int q = 0; q < 3; q++) {
        int c = tid + q * 256;
        float dv = (q == 0 ? d0 : (q == 1 ? d1 : d2));
        float v = dv * inv * s[c] + b[c];
        oh[base + c] = __float2half(v);
        if (ofp) ofp[base + c] = v;
    }
}

// ---------------- HMMA primitives ----------------
__device__ __forceinline__ void ldsm4(uint32_t& r0, uint32_t& r1, uint32_t& r2, uint32_t& r3,
                                      uint32_t addr) {
    asm volatile("ldmatrix.sync.aligned.m8n8.x4.shared.b16 {%0,%1,%2,%3}, [%4];"
                 : "=r"(r0), "=r"(r1), "=r"(r2), "=r"(r3) : "r"(addr));
}
__device__ __forceinline__ void mma16816(float* d, const uint32_t* a, const uint32_t* b) {
    asm volatile("mma.sync.aligned.m16n8k16.row.col.f32.f16.f16.f32 "
                 "{%0,%1,%2,%3}, {%4,%5,%6,%7}, {%8,%9}, {%0,%1,%2,%3};"
                 : "+f"(d[0]), "+f"(d[1]), "+f"(d[2]), "+f"(d[3])
                 : "r"(a[0]), "r"(a[1]), "r"(a[2]), "r"(a[3]), "r"(b[0]), "r"(b[1]));
}

#define ROWB 144

// ---------------- templated fp16 GEMM: C[M,N] = A[M,K]*B[N,K]^T, fp32 acc ------
// CTA tile (MTILES*32) x (NT*32); 8 warps as 2x4; warp tile (MTILES*16) x (NT*8).
// K-chunk 64, cp.async double buffer. MTILES=4,NT=4 is bit-identical to the
// proven R10 kernel. MTILES=2 (64-row tiles) doubles CTAs for small-grid GEMMs.
// mode: 0 normal | 1 gelu(bias) | 2 qkv split scatter. swapxy: m fast.
template<int MTILES, int NT, int MINB>
__global__ __launch_bounds__(256, MINB) void gemm_mm(
    const __half* __restrict__ A, const __half* __restrict__ Bm,
    int N, int K,
    const float* __restrict__ bias, const float* __restrict__ resid,
    float* __restrict__ Cf, __half* __restrict__ Ch, int mode, int swapxy)
{
    constexpr int CTA_M = MTILES * 32;
    constexpr int CTA_N = NT * 32;
    constexpr int OPB_A = CTA_M * ROWB;
    constexpr int OPB_B = CTA_N * ROWB;
    constexpr int STGT  = OPB_A + OPB_B;
    constexpr int NXFER = (CTA_M + CTA_N) * 8;    // 16B transfers per chunk

    extern __shared__ char smem[];
    uint32_t sb = smem_u32(smem);
    int tid = threadIdx.x, wid = tid >> 5, lane = tid & 31;
    int wm = wid >> 2, wn = wid & 3;
    int m0 = (swapxy ? blockIdx.x : blockIdx.y) * CTA_M;
    int n0 = (swapxy ? blockIdx.y : blockIdx.x) * CTA_N;

    auto load_chunk = [&](int c) {
        int kt = c << 6;
        uint32_t st = sb + (c & 1) * STGT;
        #pragma unroll
        for (int o = 0; o < NXFER / 256; o++) {
            int flat = o * 256 + tid;
            uint32_t dst;
            const __half* src;
            if (flat < CTA_M * 8) {               // A: CTA_M rows x 8
                int row = flat >> 3, c16 = flat & 7;
                dst = st + row * ROWB + c16 * 16;
                src = A + (size_t)(m0 + row) * K + kt + c16 * 8;
            } else {                              // B: CTA_N rows x 8
                int v = flat - CTA_M * 8;
                int row = v >> 3, c16 = v & 7;
                dst = st + OPB_A + row * ROWB + c16 * 16;
                int r = n0 + row; if (r >= N) r = N - 1;
                src = Bm + (size_t)r * K + kt + c16 * 8;
            }
            asm volatile("cp.async.cg.shared.global [%0], [%1], 16;" :: "r"(dst), "l"(src));
        }
        asm volatile("cp.async.commit_group;" ::: "memory");
    };

    float acc[MTILES][NT][4] = {};
    int nc = K >> 6;

    load_chunk(0);
    load_chunk(1);

    for (int c = 0; c < nc; c++) {
        if (c + 1 < nc) asm volatile("cp.async.wait_group 1;" ::: "memory");
        else            asm volatile("cp.async.wait_group 0;" ::: "memory");
        __syncthreads();
        uint32_t st = sb + (c & 1) * STGT;
        uint32_t a_row = (uint32_t)(wm * (MTILES * 16) + (lane & 15)) * ROWB + (lane >> 4) * 16;
        uint32_t b_row = (uint32_t)(wn * (NT * 8) + (lane & 7) + ((lane >> 4) & 1) * 8) * ROWB
                       + ((lane >> 3) & 1) * 16;
        #pragma unroll
        for (int kk = 0; kk < 4; kk++) {
            uint32_t ah[MTILES][4], bh[NT][2];
            #pragma unroll
            for (int mt = 0; mt < MTILES; mt++) {
                uint32_t ad = st + a_row + mt * (16 * ROWB) + kk * 32;
                ldsm4(ah[mt][0], ah[mt][1], ah[mt][2], ah[mt][3], ad);
            }
            #pragma unroll
            for (int np = 0; np < NT / 2; np++) {
                uint32_t bd = st + OPB_A + b_row + np * (16 * ROWB) + kk * 32;
                ldsm4(bh[np*2][0], bh[np*2][1], bh[np*2+1][0], bh[np*2+1][1], bd);
            }
            #pragma unroll
            for (int mt = 0; mt < MTILES; mt++)
                #pragma unroll
                for (int nt = 0; nt < NT; nt++)
                    mma16816(acc[mt][nt], ah[mt], bh[nt]);
        }
        __syncthreads();
        if (c + 2 < nc) load_chunk(c + 2);
    }

    #pragma unroll
    for (int mt = 0; mt < MTILES; mt++) {
        #pragma unroll
        for (int nt = 0; nt < NT; nt++) {
            int mbase = m0 + wm * (MTILES * 16) + mt * 16 + (lane >> 2);
            int nbase = n0 + wn * (NT * 8) + nt * 8 + (lane & 3) * 2;
            #pragma unroll
            for (int hrow = 0; hrow < 2; hrow++) {
                int m = mbase + hrow * 8;
                #pragma unroll
                for (int jj = 0; jj < 2; jj++) {
                    int n = nbase + jj;
                    float v = acc[mt][nt][hrow * 2 + jj];
                    if (mode == 2) {
                        int sct = n / Dd, r = n - sct * Dd;
                        int h = r / HDim, hd = r - h * HDim;
                        int bb = m >> 9, t = m & (Tt - 1);
                        int bh_ = bb * Hh + h;
                        if (sct == 0) {
                            size_t ix = ((size_t)bh_ * Tt + t) * HDP + hd;
                            __half hv = __float2half(v);
                            g_qh[ix] = hv;
                            g_ql[ix] = __float2half(v - __half2float(hv));
                        } else if (sct == 1) {
                            size_t ix = ((size_t)bh_ * Tt + t) * HDP + hd;
                            __half hv = __float2half(v);
                            g_kh[ix] = hv;
                            g_kl[ix] = __float2half(v - __half2float(hv));
                        } else {
                            g_vth[((size_t)bh_ * HDim + hd) * Tt + t] = __float2half(v);
                        }
                    } else if (n < N) {
                        if (bias) v += bias[n];
                        if (mode == 1) v = 0.5f * v * (1.0f + erff(v * 0.70710678118654752f));
                        size_t ix = (size_t)m * N + n;
                        if (resid) v += resid[ix];
                        if (Cf) Cf[ix] = v;
                        if (Ch) Ch[ix] = __float2half(v);
                    }
                }
            }
        }
    }
}

#define SMEM_MM44 (2*(128+128)*ROWB)   // 73728
#define SMEM_MM24 (2*(64+128)*ROWB)    // 55296

// ---------------- fused flash attention (proven in R10; unchanged) ----------------
#define QROWB 272
#define VROWB 144
#define FQ_OP (128*QROWB)
#define FK_OP (64*QROWB)
#define FV_OP (96*VROWB)
#define FSTGB (2*FK_OP + FV_OP)
#define SMEM_FA (2*FQ_OP + 2*FSTGB)  // 166912

__global__ __launch_bounds__(256, 1) void flash_attn(
    const __half* __restrict__ Qh, const __half* __restrict__ Ql,
    const __half* __restrict__ Kh, const __half* __restrict__ Kl,
    const __half* __restrict__ Vt, __half* __restrict__ Oo)
{
    extern __shared__ char smem[];
    uint32_t sb = smem_u32(smem);
    int tid = threadIdx.x, wid = tid >> 5, lane = tid & 31;
    int mt = blockIdx.x, z = blockIdx.y;
    int m0 = mt * 128;
    int niter = 2 * (mt + 1);

    const __half* qhp = Qh + (size_t)z * Tt * HDP;
    const __half* qlp = Ql + (size_t)z * Tt * HDP;
    const __half* khp = Kh + (size_t)z * Tt * HDP;
    const __half* klp = Kl + (size_t)z * Tt * HDP;
    const __half* vtp = Vt + (size_t)z * HDim * Tt;

    #pragma unroll
    for (int u0 = 0; u0 < 16; u0++) {
        int u = u0 * 256 + tid;
        int hi = (u < 2048);
        int v = u & 2047;
        int row = v >> 4, c16 = v & 15;
        uint32_t dst = sb + (hi ? 0 : FQ_OP) + row * QROWB + c16 * 16;
        const __half* src = (hi ? qhp : qlp) + (size_t)(m0 + row) * HDP + c16 * 8;
        asm volatile("cp.async.cg.shared.global [%0], [%1], 16;" :: "r"(dst), "l"(src));
    }
    asm volatile("cp.async.commit_group;" ::: "memory");

    auto load_kv = [&](int i) {
        int k0 = i * 64;
        uint32_t st = sb + 2 * FQ_OP + (i & 1) * FSTGB;
        #pragma unroll
        for (int u0 = 0; u0 < 11; u0++) {
            int u = u0 * 256 + tid;
            if (u < 2048) {
                int hi = (u < 1024);
                int v = u & 1023;
                int row = v >> 4, c16 = v & 15;
                uint32_t dst = st + (hi ? 0 : FK_OP) + row * QROWB + c16 * 16;
                const __half* src = (hi ? khp : klp) + (size_t)(k0 + row) * HDP + c16 * 8;
                asm volatile("cp.async.cg.shared.global [%0], [%1], 16;" :: "r"(dst), "l"(src));
            } else {
                int v = u - 2048;
                int row = v >> 3, c16 = v & 7;
                uint32_t dst = st + 2 * FK_OP + row * VROWB + c16 * 16;
                const __half* src = vtp + (size_t)row * Tt + k0 + c16 * 8;
                asm volatile("cp.async.cg.shared.global [%0], [%1], 16;" :: "r"(dst), "l"(src));
            }
        }
        asm volatile("cp.async.commit_group;" ::: "memory");
    };

    load_kv(0);
    load_kv(1);

    float o[12][4] = {};
    float m_r = -1e30f, m_r8 = -1e30f, l_r = 0.f, l_r8 = 0.f;
    int qrow = m0 + wid * 16 + (lane >> 2);

    for (int i = 0; i < niter; i++) {
        if (i + 1 < niter) asm volatile("cp.async.wait_group 1;" ::: "memory");
        else               asm volatile("cp.async.wait_group 0;" ::: "memory");
        __syncthreads();
        uint32_t st = sb + 2 * FQ_OP + (i & 1) * FSTGB;
        int k0 = i * 64;

        float sacc[8][4] = {};
        uint32_t aqbase = sb + (uint32_t)(wid * 16 + (lane & 15)) * QROWB + (lane >> 4) * 16;
        uint32_t bkbase = st + (uint32_t)((lane & 7) + ((lane >> 4) & 1) * 8) * QROWB
                        + ((lane >> 3) & 1) * 16;
        #pragma unroll
        for (int kk = 0; kk < 8; kk++) {
            uint32_t ah[4], al[4];
            ldsm4(ah[0], ah[1], ah[2], ah[3], aqbase + kk * 32);
            ldsm4(al[0], al[1], al[2], al[3], aqbase + FQ_OP + kk * 32);
            #pragma unroll
            for (int np = 0; np < 4; np++) {
                uint32_t bh0[2], bh1[2], bl0[2], bl1[2];
                uint32_t bd = bkbase + np * (16 * QROWB) + kk * 32;
                ldsm4(bh0[0], bh0[1], bh1[0], bh1[1], bd);
                ldsm4(bl0[0], bl0[1], bl1[0], bl1[1], bd + FK_OP);
                mma16816(sacc[np*2],   ah, bh0);
                mma16816(sacc[np*2+1], ah, bh1);
                mma16816(sacc[np*2],   al, bh0);
                mma16816(sacc[np*2+1], al, bh1);
                mma16816(sacc[np*2],   ah, bl0);
                mma16816(sacc[np*2+1], ah, bl1);
            }
        }

        float tmax_r = -1e30f, tmax_r8 = -1e30f;
        #pragma unroll
        for (int t = 0; t < 8; t++) {
            #pragma unroll
            for (int jj = 0; jj < 2; jj++) {
                int kcol = k0 + t * 8 + (lane & 3) * 2 + jj;
                float s0 = (kcol <= qrow)     ? sacc[t][jj]     * ATT_SCALE : -1e30f;
                float s1 = (kcol <= qrow + 8) ? sacc[t][2 + jj] * ATT_SCALE : -1e30f;
                sacc[t][jj] = s0; sacc[t][2 + jj] = s1;
                tmax_r  = fmaxf(tmax_r, s0);
                tmax_r8 = fmaxf(tmax_r8, s1);
            }
        }
        tmax_r  = fmaxf(tmax_r,  __shfl_xor_sync(0xffffffffu, tmax_r, 1));
        tmax_r  = fmaxf(tmax_r,  __shfl_xor_sync(0xffffffffu, tmax_r, 2));
        tmax_r8 = fmaxf(tmax_r8, __shfl_xor_sync(0xffffffffu, tmax_r8, 1));
        tmax_r8 = fmaxf(tmax_r8, __shfl_xor_sync(0xffffffffu, tmax_r8, 2));
        float mn_r = fmaxf(m_r, tmax_r), mn_r8 = fmaxf(m_r8, tmax_r8);
        float f_r = __expf(m_r - mn_r), f_r8 = __expf(m_r8 - mn_r8);
        m_r = mn_r; m_r8 = mn_r8;

        uint32_t pr[8], pr8[8];
        float ls_r = 0.f, ls_r8 = 0.f;
        #pragma unroll
        for (int t = 0; t < 8; t++) {
            float p0 = __expf(sacc[t][0] - m_r);
            float p1 = __expf(sacc[t][1] - m_r);
            float p2 = __expf(sacc[t][2] - m_r8);
            float p3 = __expf(sacc[t][3] - m_r8);
            ls_r += p0 + p1; ls_r8 += p2 + p3;
            __half2 h01 = __floats2half2_rn(p0, p1);
            __half2 h23 = __floats2half2_rn(p2, p3);
            pr[t]  = *(uint32_t*)&h01;
            pr8[t] = *(uint32_t*)&h23;
        }
        ls_r  += __shfl_xor_sync(0xffffffffu, ls_r, 1);
        ls_r  += __shfl_xor_sync(0xffffffffu, ls_r, 2);
        ls_r8 += __shfl_xor_sync(0xffffffffu, ls_r8, 1);
        ls_r8 += __shfl_xor_sync(0xffffffffu, ls_r8, 2);
        l_r  = l_r  * f_r  + ls_r;
        l_r8 = l_r8 * f_r8 + ls_r8;
        #pragma unroll
        for (int t = 0; t < 12; t++) {
            o[t][0] *= f_r;  o[t][1] *= f_r;
            o[t][2] *= f_r8; o[t][3] *= f_r8;
        }

        uint32_t bvbase = st + 2 * FK_OP
                        + (uint32_t)((lane & 7) + ((lane >> 4) & 1) * 8) * VROWB
                        + ((lane >> 3) & 1) * 16;
        #pragma unroll
        for (int j = 0; j < 4; j++) {
            uint32_t a[4] = { pr[2*j], pr8[2*j], pr[2*j+1], pr8[2*j+1] };
            #pragma unroll
            for (int np = 0; np < 6; np++) {
                uint32_t bv0[2], bv1[2];
                ldsm4(bv0[0], bv0[1], bv1[0], bv1[1], bvbase + np * (16 * VROWB) + j * 32);
                mma16816(o[np*2],   a, bv0);
                mma16816(o[np*2+1], a, bv1);
            }
        }
        __syncthreads();
        if (i + 2 < niter) load_kv(i + 2);
    }

    float inv_r = 1.f / l_r, inv_r8 = 1.f / l_r8;
    int bb = z >> 3, h = z & 7;
    size_t base = (size_t)bb * Tt * Dd + (size_t)h * HDim;
    #pragma unroll
    for (int t = 0; t < 12; t++) {
        int n = t * 8 + (lane & 3) * 2;
        size_t ixr  = base + (size_t)qrow * Dd + n;
        size_t ixr8 = base + (size_t)(qrow + 8) * Dd + n;
        Oo[ixr]      = __float2half(o[t][0] * inv_r);
        Oo[ixr + 1]  = __float2half(o[t][1] * inv_r);
        Oo[ixr8]     = __float2half(o[t][2] * inv_r8);
        Oo[ixr8 + 1] = __float2half(o[t][3] * inv_r8);
    }
}

// ---------------- launch ----------------
extern "C" void kernel_launch(void* const* d_in, const int* in_sizes, int n_in,
                              void* d_out, int out_size) {
    const int*   idx    = (const int*)  d_in[0];
    const float* tok    = (const float*)d_in[1];
    const float* pos    = (const float*)d_in[2];
    const float* ln1_s  = (const float*)d_in[3];
    const float* ln1_b  = (const float*)d_in[4];
    const float* qkv_w  = (const float*)d_in[5];
    const float* out_w  = (const float*)d_in[6];
    const float* ln2_s  = (const float*)d_in[7];
    const float* ln2_b  = (const float*)d_in[8];
    const float* ffn_w1 = (const float*)d_in[9];
    const float* ffn_b1 = (const float*)d_in[10];
    const float* ffn_w2 = (const float*)d_in[11];
    const float* ffn_b2 = (const float*)d_in[12];
    const float* fn_s   = (const float*)d_in[13];
    const float* fn_b   = (const float*)d_in[14];
    const float* head_w = (const float*)d_in[15];

    float* logits = (float*)d_out;
    float* hidden = logits + (size_t)Bz * Tt * Vv;

    float *x;
    __half *h16, *f16, *qh, *ql, *kh, *kl, *vth, *oh;
    __half *wq, *wo, *w1, *w2, *wh;
    cudaGetSymbolAddress((void**)&x,   g_x);
    cudaGetSymbolAddress((void**)&h16, g_h16);
    cudaGetSymbolAddress((void**)&f16, g_f16);
    cudaGetSymbolAddress((void**)&qh,  g_qh);  cudaGetSymbolAddress((void**)&ql, g_ql);
    cudaGetSymbolAddress((void**)&kh,  g_kh);  cudaGetSymbolAddress((void**)&kl, g_kl);
    cudaGetSymbolAddress((void**)&vth, g_vth);
    cudaGetSymbolAddress((void**)&oh,  g_oh);
    cudaGetSymbolAddress((void**)&wq,  g_wq);
    cudaGetSymbolAddress((void**)&wo,  g_wo);
    cudaGetSymbolAddress((void**)&w1,  g_w1);
    cudaGetSymbolAddress((void**)&w2,  g_w2);
    cudaGetSymbolAddress((void**)&wh,  g_wh);

    cudaFuncSetAttribute((const void*)gemm_mm<4,4,2>, cudaFuncAttributeMaxDynamicSharedMemorySize, SMEM_MM44);
    cudaFuncSetAttribute((const void*)gemm_mm<2,4,2>, cudaFuncAttributeMaxDynamicSharedMemorySize, SMEM_MM24);
    cudaFuncSetAttribute(flash_attn, cudaFuncAttributeMaxDynamicSharedMemorySize, SMEM_FA);

    size_t n1 = (size_t)Ll * 3 * Dd * Dd / 4;
    size_t n2 = (size_t)Ll * Dd * Dd / 4;
    size_t n3 = (size_t)Ll * 4 * Dd * Dd / 4;
    size_t n5 = (size_t)Vv * Dd / 4;

    // launch order: cvt_wq, embed, ln, qkv-gemm FIRST so the fixed ncu capture
    // slot lands on gemm_mm<4,4,2> instead of a cvt kernel.
    cvt_k<<<(unsigned)((n1 + 255) / 256), 256>>>(qkv_w,  wq, n1);
    embed_k<<<(MR * Dd) / 256, 256>>>(idx, tok, pos, x);
    ln_k<<<MR, 256>>>(x, ln1_s, ln1_b, h16, nullptr);
    gemm_mm<4,4,2><<<dim3(18, 16), 256, SMEM_MM44>>>(h16, wq, 3 * Dd, Dd,
                                                     nullptr, nullptr, nullptr, nullptr, 2, 0);
    cvt_k<<<(unsigned)((n2 + 255) / 256), 256>>>(out_w,  wo, n2);
    cvt_k<<<(unsigned)((n3 + 255) / 256), 256>>>(ffn_w1, w1, n3);
    cvt_k<<<(unsigned)((n3 + 255) / 256), 256>>>(ffn_w2, w2, n3);
    cvt_k<<<(unsigned)((n5 + 255) / 256), 256>>>(head_w, wh, n5);

    for (int l = 0; l < Ll; l++) {
        if (l > 0) {
            ln_k<<<MR, 256>>>(x, ln1_s + l * Dd, ln1_b + l * Dd, h16, nullptr);
            gemm_mm<4,4,2><<<dim3(18, 16), 256, SMEM_MM44>>>(h16, wq + (size_t)l * 3 * Dd * Dd,
                                                             3 * Dd, Dd, nullptr, nullptr,
                                                             nullptr, nullptr, 2, 0);
        }
        flash_attn<<<dim3(4, BH), 256, SMEM_FA>>>(qh, ql, kh, kl, vth, oh);
        gemm_mm<2,4,2><<<dim3(6, 32), 256, SMEM_MM24>>>(oh, wo + (size_t)l * Dd * Dd,
                                                        Dd, Dd, nullptr, x, x, nullptr, 0, 0);
        ln_k<<<MR, 256>>>(x, ln2_s + l * Dd, ln2_b + l * Dd, h16, nullptr);
        gemm_mm<4,4,2><<<dim3(24, 16), 256, SMEM_MM44>>>(h16, w1 + (size_t)l * 4 * Dd * Dd,
                                                         4 * Dd, Dd, ffn_b1 + l * 4 * Dd, nullptr,
                                                         nullptr, f16, 1, 0);
        gemm_mm<2,4,2><<<dim3(6, 32), 256, SMEM_MM24>>>(f16, w2 + (size_t)l * 4 * Dd * Dd,
                                                        Dd, 4 * Dd, ffn_b2 + l * Dd, x, x, nullptr, 0, 0);
    }

    ln_k<<<MR, 256>>>(x, fn_s, fn_b, h16, hidden);
    // head GEMM: swapxy=1 so a scheduling wave shares weight tiles (B streamed once)
    gemm_mm<4,4,2><<<dim3(16, 393), 256, SMEM_MM44>>>(h16, wh, Vv, Dd,
                                                      nullptr, nullptr, logits, nullptr, 0, 1);
}

// round 16
// speedup vs baseline: 2.9258x; 1.0251x over previous
#include <cuda_runtime.h>
#include <cuda_fp16.h>
#include <math.h>
#include <stdint.h>

#define Bz   4
#define Tt   512
#define Dd   768
#define Hh   8
#define HDim 96
#define HDP  128            // padded head dim for MMA (pad cols stay zero: globals zero-init)
#define Ll   12
#define Vv   50257
#define MR   (Bz*Tt)
#define BH   (Bz*Hh)
#define ATT_SCALE 0.10206207261596575f

__device__ __forceinline__ uint32_t smem_u32(const void* p) {
    uint32_t a;
    asm("{ .reg .u64 t; cvta.to.shared.u64 t, %1; cvt.u32.u64 %0, t; }" : "=r"(a) : "l"(p));
    return a;
}

// ---------------- scratch (device globals) ----------------
__device__ float g_x [MR*Dd];
__device__ __align__(16) __half g_h16[MR*Dd];
__device__ __align__(16) __half g_f16[MR*4*Dd];
__device__ __align__(16) __half g_qh[(size_t)BH*Tt*HDP], g_ql[(size_t)BH*Tt*HDP];
__device__ __align__(16) __half g_kh[(size_t)BH*Tt*HDP], g_kl[(size_t)BH*Tt*HDP];
__device__ __align__(16) __half g_vth[(size_t)BH*HDim*Tt];
__device__ __align__(16) __half g_oh[MR*Dd];
__device__ __align__(16) __half g_wq[(size_t)Ll*3*Dd*Dd];
__device__ __align__(16) __half g_wo[(size_t)Ll*Dd*Dd];
__device__ __align__(16) __half g_w1[(size_t)Ll*4*Dd*Dd];
__device__ __align__(16) __half g_w2[(size_t)Ll*4*Dd*Dd];
__device__ __align__(16) __half g_wh[(size_t)Vv*Dd];

// ---------------- weight fp32 -> fp16 ----------------
__global__ void cvt_k(const float* __restrict__ w, __half* __restrict__ o, size_t n4) {
    size_t i = (size_t)blockIdx.x * 256 + threadIdx.x;
    if (i >= n4) return;
    float4 v = ((const float4*)w)[i];
    ((__half2*)o)[i * 2]     = __floats2half2_rn(v.x, v.y);
    ((__half2*)o)[i * 2 + 1] = __floats2half2_rn(v.z, v.w);
}

// ---------------- embedding ----------------
__global__ void embed_k(const int* __restrict__ idx, const float* __restrict__ tok,
                        const float* __restrict__ pos, float* __restrict__ x) {
    int i = blockIdx.x * 256 + threadIdx.x;
    int m = i / Dd, d = i - m * Dd;
    int t = m & (Tt - 1);
    x[i] = tok[(size_t)idx[m] * Dd + d] + pos[t * Dd + d];
}

// ---------------- layernorm -> fp16 (+ optional fp32) ----------------
__global__ void ln_k(const float* __restrict__ in, const float* __restrict__ s,
                     const float* __restrict__ b, __half* __restrict__ oh,
                     float* __restrict__ ofp) {
    int m = blockIdx.x, tid = threadIdx.x;
    const float* row = in + (size_t)m * Dd;
    float x0 = row[tid], x1 = row[tid + 256], x2 = row[tid + 512];
    __shared__ float red[256];
    red[tid] = x0 + x1 + x2;
    __syncthreads();
    #pragma unroll
    for (int st = 128; st > 0; st >>= 1) { if (tid < st) red[tid] += red[tid + st]; __syncthreads(); }
    float mean = red[0] * (1.0f / Dd);
    __syncthreads();
    float d0 = x0 - mean, d1 = x1 - mean, d2 = x2 - mean;
    red[tid] = d0 * d0 + d1 * d1 + d2 * d2;
    __syncthreads();
    #pragma unroll
    for (int st = 128; st > 0; st >>= 1) { if (tid < st) red[tid] += red[tid + st]; __syncthreads(); }
    float inv = rsqrtf(red[0] * (1.0f / Dd) + 1e-5f);
    size_t base = (size_t)m * Dd;
    #pragma unroll
    for (int q = 0; q < 3; q++) {
        int c = tid + q * 256;
        float dv = (q == 0 ? d0 : (q == 1 ? d1 : d2));
        float v = dv * inv * s[c] + b[c];
        oh[base + c] = __float2half(v);
        if (ofp) ofp[base + c] = v;
    }
}

// ---------------- HMMA primitives ----------------
__device__ __forceinline__ void ldsm4(uint32_t& r0, uint32_t& r1, uint32_t& r2, uint32_t& r3,
                                      uint32_t addr) {
    asm volatile("ldmatrix.sync.aligned.m8n8.x4.shared.b16 {%0,%1,%2,%3}, [%4];"
                 : "=r"(r0), "=r"(r1), "=r"(r2), "=r"(r3) : "r"(addr));
}
__device__ __forceinline__ void mma16816(float* d, const uint32_t* a, const uint32_t* b) {
    asm volatile("mma.sync.aligned.m16n8k16.row.col.f32.f16.f16.f32 "
                 "{%0,%1,%2,%3}, {%4,%5,%6,%7}, {%8,%9}, {%0,%1,%2,%3};"
                 : "+f"(d[0]), "+f"(d[1]), "+f"(d[2]), "+f"(d[3])
                 : "r"(a[0]), "r"(a[1]), "r"(a[2]), "r"(a[3]), "r"(b[0]), "r"(b[1]));
}

#define ROWB 144

// ---------------- templated fp16 GEMM: C[M,N] = A[M,K]*B[N,K]^T, fp32 acc ------
// CTA tile (MTILES*32) x (NT*32); 8 warps as 2x4; warp tile (MTILES*16) x (NT*8).
// K-chunk 64, cp.async double buffer. MTILES=4,NT=4 is bit-identical to the
// proven R10 kernel. MTILES=2 + MINB=3 trades acc registers for occupancy
// (24 warps/SM) on the latency-bound layer GEMMs.
// mode: 0 normal | 1 gelu(bias) | 2 qkv split scatter. swapxy: m fast.
template<int MTILES, int NT, int MINB>
__global__ __launch_bounds__(256, MINB) void gemm_mm(
    const __half* __restrict__ A, const __half* __restrict__ Bm,
    int N, int K,
    const float* __restrict__ bias, const float* __restrict__ resid,
    float* __restrict__ Cf, __half* __restrict__ Ch, int mode, int swapxy)
{
    constexpr int CTA_M = MTILES * 32;
    constexpr int CTA_N = NT * 32;
    constexpr int OPB_A = CTA_M * ROWB;
    constexpr int OPB_B = CTA_N * ROWB;
    constexpr int STGT  = OPB_A + OPB_B;
    constexpr int NXFER = (CTA_M + CTA_N) * 8;    // 16B transfers per chunk

    extern __shared__ char smem[];
    uint32_t sb = smem_u32(smem);
    int tid = threadIdx.x, wid = tid >> 5, lane = tid & 31;
    int wm = wid >> 2, wn = wid & 3;
    int m0 = (swapxy ? blockIdx.x : blockIdx.y) * CTA_M;
    int n0 = (swapxy ? blockIdx.y : blockIdx.x) * CTA_N;

    auto load_chunk = [&](int c) {
        int kt = c << 6;
        uint32_t st = sb + (c & 1) * STGT;
        #pragma unroll
        for (int o = 0; o < NXFER / 256; o++) {
            int flat = o * 256 + tid;
            uint32_t dst;
            const __half* src;
            if (flat < CTA_M * 8) {               // A: CTA_M rows x 8
                int row = flat >> 3, c16 = flat & 7;
                dst = st + row * ROWB + c16 * 16;
                src = A + (size_t)(m0 + row) * K + kt + c16 * 8;
            } else {                              // B: CTA_N rows x 8
                int v = flat - CTA_M * 8;
                int row = v >> 3, c16 = v & 7;
                dst = st + OPB_A + row * ROWB + c16 * 16;
                int r = n0 + row; if (r >= N) r = N - 1;
                src = Bm + (size_t)r * K + kt + c16 * 8;
            }
            asm volatile("cp.async.cg.shared.global [%0], [%1], 16;" :: "r"(dst), "l"(src));
        }
        asm volatile("cp.async.commit_group;" ::: "memory");
    };

    float acc[MTILES][NT][4] = {};
    int nc = K >> 6;

    load_chunk(0);
    load_chunk(1);

    for (int c = 0; c < nc; c++) {
        if (c + 1 < nc) asm volatile("cp.async.wait_group 1;" ::: "memory");
        else            asm volatile("cp.async.wait_group 0;" ::: "memory");
        __syncthreads();
        uint32_t st = sb + (c & 1) * STGT;
        uint32_t a_row = (uint32_t)(wm * (MTILES * 16) + (lane & 15)) * ROWB + (lane >> 4) * 16;
        uint32_t b_row = (uint32_t)(wn * (NT * 8) + (lane & 7) + ((lane >> 4) & 1) * 8) * ROWB
                       + ((lane >> 3) & 1) * 16;
        #pragma unroll
        for (int kk = 0; kk < 4; kk++) {
            uint32_t ah[MTILES][4], bh[NT][2];
            #pragma unroll
            for (int mt = 0; mt < MTILES; mt++) {
                uint32_t ad = st + a_row + mt * (16 * ROWB) + kk * 32;
                ldsm4(ah[mt][0], ah[mt][1], ah[mt][2], ah[mt][3], ad);
            }
            #pragma unroll
            for (int np = 0; np < NT / 2; np++) {
                uint32_t bd = st + OPB_A + b_row + np * (16 * ROWB) + kk * 32;
                ldsm4(bh[np*2][0], bh[np*2][1], bh[np*2+1][0], bh[np*2+1][1], bd);
            }
            #pragma unroll
            for (int mt = 0; mt < MTILES; mt++)
                #pragma unroll
                for (int nt = 0; nt < NT; nt++)
                    mma16816(acc[mt][nt], ah[mt], bh[nt]);
        }
        __syncthreads();
        if (c + 2 < nc) load_chunk(c + 2);
    }

    #pragma unroll
    for (int mt = 0; mt < MTILES; mt++) {
        #pragma unroll
        for (int nt = 0; nt < NT; nt++) {
            int mbase = m0 + wm * (MTILES * 16) + mt * 16 + (lane >> 2);
            int nbase = n0 + wn * (NT * 8) + nt * 8 + (lane & 3) * 2;
            #pragma unroll
            for (int hrow = 0; hrow < 2; hrow++) {
                int m = mbase + hrow * 8;
                #pragma unroll
                for (int jj = 0; jj < 2; jj++) {
                    int n = nbase + jj;
                    float v = acc[mt][nt][hrow * 2 + jj];
                    if (mode == 2) {
                        int sct = n / Dd, r = n - sct * Dd;
                        int h = r / HDim, hd = r - h * HDim;
                        int bb = m >> 9, t = m & (Tt - 1);
                        int bh_ = bb * Hh + h;
                        if (sct == 0) {
                            size_t ix = ((size_t)bh_ * Tt + t) * HDP + hd;
                            __half hv = __float2half(v);
                            g_qh[ix] = hv;
                            g_ql[ix] = __float2half(v - __half2float(hv));
                        } else if (sct == 1) {
                            size_t ix = ((size_t)bh_ * Tt + t) * HDP + hd;
                            __half hv = __float2half(v);
                            g_kh[ix] = hv;
                            g_kl[ix] = __float2half(v - __half2float(hv));
                        } else {
                            g_vth[((size_t)bh_ * HDim + hd) * Tt + t] = __float2half(v);
                        }
                    } else if (n < N) {
                        if (bias) v += bias[n];
                        if (mode == 1) v = 0.5f * v * (1.0f + erff(v * 0.70710678118654752f));
                        size_t ix = (size_t)m * N + n;
                        if (resid) v += resid[ix];
                        if (Cf) Cf[ix] = v;
                        if (Ch) Ch[ix] = __float2half(v);
                    }
                }
            }
        }
    }
}

#define SMEM_MM44 (2*(128+128)*ROWB)   // 73728
#define SMEM_MM24 (2*(64+128)*ROWB)    // 55296

// ---------------- fused flash attention (proven in R10; unchanged) ----------------
#define QROWB 272
#define VROWB 144
#define FQ_OP (128*QROWB)
#define FK_OP (64*QROWB)
#define FV_OP (96*VROWB)
#define FSTGB (2*FK_OP + FV_OP)
#define SMEM_FA (2*FQ_OP + 2*FSTGB)  // 166912

__global__ __launch_bounds__(256, 1) void flash_attn(
    const __half* __restrict__ Qh, const __half* __restrict__ Ql,
    const __half* __restrict__ Kh, const __half* __restrict__ Kl,
    const __half* __restrict__ Vt, __half* __restrict__ Oo)
{
    extern __shared__ char smem[];
    uint32_t sb = smem_u32(smem);
    int tid = threadIdx.x, wid = tid >> 5, lane = tid & 31;
    int mt = blockIdx.x, z = blockIdx.y;
    int m0 = mt * 128;
    int niter = 2 * (mt + 1);

    const __half* qhp = Qh + (size_t)z * Tt * HDP;
    const __half* qlp = Ql + (size_t)z * Tt * HDP;
    const __half* khp = Kh + (size_t)z * Tt * HDP;
    const __half* klp = Kl + (size_t)z * Tt * HDP;
    const __half* vtp = Vt + (size_t)z * HDim * Tt;

    #pragma unroll
    for (int u0 = 0; u0 < 16; u0++) {
        int u = u0 * 256 + tid;
        int hi = (u < 2048);
        int v = u & 2047;
        int row = v >> 4, c16 = v & 15;
        uint32_t dst = sb + (hi ? 0 : FQ_OP) + row * QROWB + c16 * 16;
        const __half* src = (hi ? qhp : qlp) + (size_t)(m0 + row) * HDP + c16 * 8;
        asm volatile("cp.async.cg.shared.global [%0], [%1], 16;" :: "r"(dst), "l"(src));
    }
    asm volatile("cp.async.commit_group;" ::: "memory");

    auto load_kv = [&](int i) {
        int k0 = i * 64;
        uint32_t st = sb + 2 * FQ_OP + (i & 1) * FSTGB;
        #pragma unroll
        for (int u0 = 0; u0 < 11; u0++) {
            int u = u0 * 256 + tid;
            if (u < 2048) {
                int hi = (u < 1024);
                int v = u & 1023;
                int row = v >> 4, c16 = v & 15;
                uint32_t dst = st + (hi ? 0 : FK_OP) + row * QROWB + c16 * 16;
                const __half* src = (hi ? khp : klp) + (size_t)(k0 + row) * HDP + c16 * 8;
                asm volatile("cp.async.cg.shared.global [%0], [%1], 16;" :: "r"(dst), "l"(src));
            } else {
                int v = u - 2048;
                int row = v >> 3, c16 = v & 7;
                uint32_t dst = st + 2 * FK_OP + row * VROWB + c16 * 16;
                const __half* src = vtp + (size_t)row * Tt + k0 + c16 * 8;
                asm volatile("cp.async.cg.shared.global [%0], [%1], 16;" :: "r"(dst), "l"(src));
            }
        }
        asm volatile("cp.async.commit_group;" ::: "memory");
    };

    load_kv(0);
    load_kv(1);

    float o[12][4] = {};
    float m_r = -1e30f, m_r8 = -1e30f, l_r = 0.f, l_r8 = 0.f;
    int qrow = m0 + wid * 16 + (lane >> 2);

    for (int i = 0; i < niter; i++) {
        if (i + 1 < niter) asm volatile("cp.async.wait_group 1;" ::: "memory");
        else               asm volatile("cp.async.wait_group 0;" ::: "memory");
        __syncthreads();
        uint32_t st = sb + 2 * FQ_OP + (i & 1) * FSTGB;
        int k0 = i * 64;

        float sacc[8][4] = {};
        uint32_t aqbase = sb + (uint32_t)(wid * 16 + (lane & 15)) * QROWB + (lane >> 4) * 16;
        uint32_t bkbase = st + (uint32_t)((lane & 7) + ((lane >> 4) & 1) * 8) * QROWB
                        + ((lane >> 3) & 1) * 16;
        #pragma unroll
        for (int kk = 0; kk < 8; kk++) {
            uint32_t ah[4], al[4];
            ldsm4(ah[0], ah[1], ah[2], ah[3], aqbase + kk * 32);
            ldsm4(al[0], al[1], al[2], al[3], aqbase + FQ_OP + kk * 32);
            #pragma unroll
            for (int np = 0; np < 4; np++) {
                uint32_t bh0[2], bh1[2], bl0[2], bl1[2];
                uint32_t bd = bkbase + np * (16 * QROWB) + kk * 32;
                ldsm4(bh0[0], bh0[1], bh1[0], bh1[1], bd);
                ldsm4(bl0[0], bl0[1], bl1[0], bl1[1], bd + FK_OP);
                mma16816(sacc[np*2],   ah, bh0);
                mma16816(sacc[np*2+1], ah, bh1);
                mma16816(sacc[np*2],   al, bh0);
                mma16816(sacc[np*2+1], al, bh1);
                mma16816(sacc[np*2],   ah, bl0);
                mma16816(sacc[np*2+1], ah, bl1);
            }
        }

        float tmax_r = -1e30f, tmax_r8 = -1e30f;
        #pragma unroll
        for (int t = 0; t < 8; t++) {
            #pragma unroll
            for (int jj = 0; jj < 2; jj++) {
                int kcol = k0 + t * 8 + (lane & 3) * 2 + jj;
                float s0 = (kcol <= qrow)     ? sacc[t][jj]     * ATT_SCALE : -1e30f;
                float s1 = (kcol <= qrow + 8) ? sacc[t][2 + jj] * ATT_SCALE : -1e30f;
                sacc[t][jj] = s0; sacc[t][2 + jj] = s1;
                tmax_r  = fmaxf(tmax_r, s0);
                tmax_r8 = fmaxf(tmax_r8, s1);
            }
        }
        tmax_r  = fmaxf(tmax_r,  __shfl_xor_sync(0xffffffffu, tmax_r, 1));
        tmax_r  = fmaxf(tmax_r,  __shfl_xor_sync(0xffffffffu, tmax_r, 2));
        tmax_r8 = fmaxf(tmax_r8, __shfl_xor_sync(0xffffffffu, tmax_r8, 1));
        tmax_r8 = fmaxf(tmax_r8, __shfl_xor_sync(0xffffffffu, tmax_r8, 2));
        float mn_r = fmaxf(m_r, tmax_r), mn_r8 = fmaxf(m_r8, tmax_r8);
        float f_r = __expf(m_r - mn_r), f_r8 = __expf(m_r8 - mn_r8);
        m_r = mn_r; m_r8 = mn_r8;

        uint32_t pr[8], pr8[8];
        float ls_r = 0.f, ls_r8 = 0.f;
        #pragma unroll
        for (int t = 0; t < 8; t++) {
            float p0 = __expf(sacc[t][0] - m_r);
            float p1 = __expf(sacc[t][1] - m_r);
            float p2 = __expf(sacc[t][2] - m_r8);
            float p3 = __expf(sacc[t][3] - m_r8);
            ls_r += p0 + p1; ls_r8 += p2 + p3;
            __half2 h01 = __floats2half2_rn(p0, p1);
            __half2 h23 = __floats2half2_rn(p2, p3);
            pr[t]  = *(uint32_t*)&h01;
            pr8[t] = *(uint32_t*)&h23;
        }
        ls_r  += __shfl_xor_sync(0xffffffffu, ls_r, 1);
        ls_r  += __shfl_xor_sync(0xffffffffu, ls_r, 2);
        ls_r8 += __shfl_xor_sync(0xffffffffu, ls_r8, 1);
        ls_r8 += __shfl_xor_sync(0xffffffffu, ls_r8, 2);
        l_r  = l_r  * f_r  + ls_r;
        l_r8 = l_r8 * f_r8 + ls_r8;
        #pragma unroll
        for (int t = 0; t < 12; t++) {
            o[t][0] *= f_r;  o[t][1] *= f_r;
            o[t][2] *= f_r8; o[t][3] *= f_r8;
        }

        uint32_t bvbase = st + 2 * FK_OP
                        + (uint32_t)((lane & 7) + ((lane >> 4) & 1) * 8) * VROWB
                        + ((lane >> 3) & 1) * 16;
        #pragma unroll
        for (int j = 0; j < 4; j++) {
            uint32_t a[4] = { pr[2*j], pr8[2*j], pr[2*j+1], pr8[2*j+1] };
            #pragma unroll
            for (int np = 0; np < 6; np++) {
                uint32_t bv0[2], bv1[2];
                ldsm4(bv0[0], bv0[1], bv1[0], bv1[1], bvbase + np * (16 * VROWB) + j * 32);
                mma16816(o[np*2],   a, bv0);
                mma16816(o[np*2+1], a, bv1);
            }
        }
        __syncthreads();
        if (i + 2 < niter) load_kv(i + 2);
    }

    float inv_r = 1.f / l_r, inv_r8 = 1.f / l_r8;
    int bb = z >> 3, h = z & 7;
    size_t base = (size_t)bb * Tt * Dd + (size_t)h * HDim;
    #pragma unroll
    for (int t = 0; t < 12; t++) {
        int n = t * 8 + (lane & 3) * 2;
        size_t ixr  = base + (size_t)qrow * Dd + n;
        size_t ixr8 = base + (size_t)(qrow + 8) * Dd + n;
        Oo[ixr]      = __float2half(o[t][0] * inv_r);
        Oo[ixr + 1]  = __float2half(o[t][1] * inv_r);
        Oo[ixr8]     = __float2half(o[t][2] * inv_r8);
        Oo[ixr8 + 1] = __float2half(o[t][3] * inv_r8);
    }
}

// ---------------- launch ----------------
extern "C" void kernel_launch(void* const* d_in, const int* in_sizes, int n_in,
                              void* d_out, int out_size) {
    const int*   idx    = (const int*)  d_in[0];
    const float* tok    = (const float*)d_in[1];
    const float* pos    = (const float*)d_in[2];
    const float* ln1_s  = (const float*)d_in[3];
    const float* ln1_b  = (const float*)d_in[4];
    const float* qkv_w  = (const float*)d_in[5];
    const float* out_w  = (const float*)d_in[6];
    const float* ln2_s  = (const float*)d_in[7];
    const float* ln2_b  = (const float*)d_in[8];
    const float* ffn_w1 = (const float*)d_in[9];
    const float* ffn_b1 = (const float*)d_in[10];
    const float* ffn_w2 = (const float*)d_in[11];
    const float* ffn_b2 = (const float*)d_in[12];
    const float* fn_s   = (const float*)d_in[13];
    const float* fn_b   = (const float*)d_in[14];
    const float* head_w = (const float*)d_in[15];

    float* logits = (float*)d_out;
    float* hidden = logits + (size_t)Bz * Tt * Vv;

    float *x;
    __half *h16, *f16, *qh, *ql, *kh, *kl, *vth, *oh;
    __half *wq, *wo, *w1, *w2, *wh;
    cudaGetSymbolAddress((void**)&x,   g_x);
    cudaGetSymbolAddress((void**)&h16, g_h16);
    cudaGetSymbolAddress((void**)&f16, g_f16);
    cudaGetSymbolAddress((void**)&qh,  g_qh);  cudaGetSymbolAddress((void**)&ql, g_ql);
    cudaGetSymbolAddress((void**)&kh,  g_kh);  cudaGetSymbolAddress((void**)&kl, g_kl);
    cudaGetSymbolAddress((void**)&vth, g_vth);
    cudaGetSymbolAddress((void**)&oh,  g_oh);
    cudaGetSymbolAddress((void**)&wq,  g_wq);
    cudaGetSymbolAddress((void**)&wo,  g_wo);
    cudaGetSymbolAddress((void**)&w1,  g_w1);
    cudaGetSymbolAddress((void**)&w2,  g_w2);
    cudaGetSymbolAddress((void**)&wh,  g_wh);

    cudaFuncSetAttribute((const void*)gemm_mm<4,4,2>, cudaFuncAttributeMaxDynamicSharedMemorySize, SMEM_MM44);
    cudaFuncSetAttribute((const void*)gemm_mm<2,4,3>, cudaFuncAttributeMaxDynamicSharedMemorySize, SMEM_MM24);
    cudaFuncSetAttribute(flash_attn, cudaFuncAttributeMaxDynamicSharedMemorySize, SMEM_FA);

    size_t n1 = (size_t)Ll * 3 * Dd * Dd / 4;
    size_t n2 = (size_t)Ll * Dd * Dd / 4;
    size_t n3 = (size_t)Ll * 4 * Dd * Dd / 4;
    size_t n5 = (size_t)Vv * Dd / 4;

    // launch order: cvt_wq, embed, ln, qkv-gemm FIRST so the fixed ncu capture
    // slot lands on the new gemm_mm<2,4,3> instead of a cvt kernel.
    cvt_k<<<(unsigned)((n1 + 255) / 256), 256>>>(qkv_w,  wq, n1);
    embed_k<<<(MR * Dd) / 256, 256>>>(idx, tok, pos, x);
    ln_k<<<MR, 256>>>(x, ln1_s, ln1_b, h16, nullptr);
    gemm_mm<2,4,3><<<dim3(18, 32), 256, SMEM_MM24>>>(h16, wq, 3 * Dd, Dd,
                                                     nullptr, nullptr, nullptr, nullptr, 2, 0);
    cvt_k<<<(unsigned)((n2 + 255) / 256), 256>>>(out_w,  wo, n2);
    cvt_k<<<(unsigned)((n3 + 255) / 256), 256>>>(ffn_w1, w1, n3);
    cvt_k<<<(unsigned)((n3 + 255) / 256), 256>>>(ffn_w2, w2, n3);
    cvt_k<<<(unsigned)((n5 + 255) / 256), 256>>>(head_w, wh, n5);

    for (int l = 0; l < Ll; l++) {
        if (l > 0) {
            ln_k<<<MR, 256>>>(x, ln1_s + l * Dd, ln1_b + l * Dd, h16, nullptr);
            gemm_mm<2,4,3><<<dim3(18, 32), 256, SMEM_MM24>>>(h16, wq + (size_t)l * 3 * Dd * Dd,
                                                             3 * Dd, Dd, nullptr, nullptr,
                                                             nullptr, nullptr, 2, 0);
        }
        flash_attn<<<dim3(4, BH), 256, SMEM_FA>>>(qh, ql, kh, kl, vth, oh);
        gemm_mm<2,4,3><<<dim3(6, 32), 256, SMEM_MM24>>>(oh, wo + (size_t)l * Dd * Dd,
                                                        Dd, Dd, nullptr, x, x, nullptr, 0, 0);
        ln_k<<<MR, 256>>>(x, ln2_s + l * Dd, ln2_b + l * Dd, h16, nullptr);
        gemm_mm<2,4,3><<<dim3(24, 32), 256, SMEM_MM24>>>(h16, w1 + (size_t)l * 4 * Dd * Dd,
                                                         4 * Dd, Dd, ffn_b1 + l * 4 * Dd, nullptr,
                                                         nullptr, f16, 1, 0);
        gemm_mm<2,4,3><<<dim3(6, 32), 256, SMEM_MM24>>>(f16, w2 + (size_t)l * 4 * Dd * Dd,
                                                        Dd, 4 * Dd, ffn_b2 + l * Dd, x, x, nullptr, 0, 0);
    }

    ln_k<<<MR, 256>>>(x, fn_s, fn_b, h16, hidden);
    // head GEMM stays 128x128 (halving m-tiles would double its 2.4GB L2 stream);
    // swapxy=1 so a scheduling wave shares weight tiles.
    gemm_mm<4,4,2><<<dim3(16, 393), 256, SMEM_MM44>>>(h16, wh, Vv, Dd,
                                                      nullptr, nullptr, logits, nullptr, 0, 1);
}